// round 4
// baseline (speedup 1.0000x reference)
#include <cuda_runtime.h>
#include <cuda_bf16.h>
#include <math.h>

// ---------------- problem constants ----------------
#define BB        4
#define LSEQ      2048
#define DMODEL    1024
#define DIN       2048          // D_INNER
#define NH        32            // NHEADS
#define HD        64            // HEADDIM
#define DSTATE    128
#define CONVDIM   2304          // DIN + 2*DSTATE
#define DPROJ     4384          // 2*DIN + 2*DSTATE + NH
#define MROWS     (BB*LSEQ)     // 8192

typedef unsigned long long ull;

// ---------------- scratch (static __device__, no allocs) ----------------
__device__ float g_zxbcdt[(size_t)MROWS * DPROJ];   // 143.7 MB
__device__ float g_xc[(size_t)MROWS * CONVDIM];     // 75.5 MB (conv+silu output)
__device__ float g_y[(size_t)MROWS * DIN];          // 67 MB (scan out, then normed in-place)
__device__ float g_dt[(size_t)MROWS * NH];
__device__ float g_dA[(size_t)MROWS * NH];

// ---------------- f32x2 helpers ----------------
__device__ __forceinline__ ull ffma2(ull a, ull b, ull c) {
    ull d; asm("fma.rn.f32x2 %0, %1, %2, %3;" : "=l"(d) : "l"(a), "l"(b), "l"(c)); return d;
}
__device__ __forceinline__ ull fmul2(ull a, ull b) {
    ull d; asm("mul.rn.f32x2 %0, %1, %2;" : "=l"(d) : "l"(a), "l"(b)); return d;
}
__device__ __forceinline__ ull pack2(float lo, float hi) {
    ull r; asm("mov.b64 %0, {%1, %2};" : "=l"(r) : "f"(lo), "f"(hi)); return r;
}
__device__ __forceinline__ float2 unpack2(ull v) {
    float2 f; asm("mov.b64 {%0, %1}, %2;" : "=f"(f.x), "=f"(f.y) : "l"(v)); return f;
}

// ---------------- GEMM: C[M,N] = A[M,K] @ B[K,N], fp32, f32x2 microkernel ----------------
// 128x128 block, BK=16, 256 threads, 8x8 outputs per thread (as 8 rows x 4 f32x2 col-pairs).
// A tile stored DUPLICATED in smem (each value twice) so dup-pairs load as u64 with no MOVs.
__global__ void __launch_bounds__(256)
sgemm_f32x2(const float* __restrict__ A, const float* __restrict__ B,
            float* __restrict__ C, int M, int N, int K)
{
    __shared__ __align__(16) float As2[16][256];   // [k][2*m], m in 0..127 duplicated
    __shared__ __align__(16) float Bs[16][128];

    const int tid = threadIdx.x;
    const int tx  = tid & 15;    // N direction
    const int ty  = tid >> 4;    // M direction
    const int rowBase = blockIdx.y << 7;
    const int colBase = blockIdx.x << 7;

    ull acc[8][4];
#pragma unroll
    for (int i = 0; i < 8; i++)
#pragma unroll
        for (int j = 0; j < 4; j++) acc[i][j] = 0ull;

    const int arow = tid >> 2, aq = tid & 3;        // A loader: rows arow, arow+64 ; k-quad aq
    const int brow = tid >> 5, bc4 = tid & 31;      // B loader
    const int bcol = colBase + bc4 * 4;
    const bool bvalid = (bcol < N);

    const float* Aptr0 = A + (size_t)(rowBase + arow) * K + aq * 4;
    const float* Aptr1 = Aptr0 + (size_t)64 * K;
    const float* Bptr0 = B + (size_t)brow * N + bcol;
    const float* Bptr1 = B + (size_t)(brow + 8) * N + bcol;

    float4 a0, a1, b0, b1;
    a0 = *(const float4*)(Aptr0);
    a1 = *(const float4*)(Aptr1);
    if (bvalid) { b0 = *(const float4*)(Bptr0); b1 = *(const float4*)(Bptr1); }
    else        { b0 = make_float4(0,0,0,0); b1 = b0; }

    for (int kb = 0; kb < K; kb += 16) {
        // stage to smem (A duplicated)
        *(ull*)&As2[aq*4+0][2*arow]       = pack2(a0.x, a0.x);
        *(ull*)&As2[aq*4+1][2*arow]       = pack2(a0.y, a0.y);
        *(ull*)&As2[aq*4+2][2*arow]       = pack2(a0.z, a0.z);
        *(ull*)&As2[aq*4+3][2*arow]       = pack2(a0.w, a0.w);
        *(ull*)&As2[aq*4+0][2*arow + 128] = pack2(a1.x, a1.x);
        *(ull*)&As2[aq*4+1][2*arow + 128] = pack2(a1.y, a1.y);
        *(ull*)&As2[aq*4+2][2*arow + 128] = pack2(a1.z, a1.z);
        *(ull*)&As2[aq*4+3][2*arow + 128] = pack2(a1.w, a1.w);
        *(float4*)&Bs[brow][bc4*4]     = b0;
        *(float4*)&Bs[brow+8][bc4*4]   = b1;
        __syncthreads();

        // prefetch next tile (hide global latency behind compute)
        const bool more = (kb + 16) < K;
        float4 na0, na1, nb0, nb1;
        if (more) {
            na0 = *(const float4*)(Aptr0 + kb + 16);
            na1 = *(const float4*)(Aptr1 + kb + 16);
            if (bvalid) { nb0 = *(const float4*)(Bptr0 + (size_t)(kb + 16) * N);
                          nb1 = *(const float4*)(Bptr1 + (size_t)(kb + 16) * N); }
            else        { nb0 = make_float4(0,0,0,0); nb1 = nb0; }
        }

#pragma unroll
        for (int kk = 0; kk < 16; kk++) {
            ulonglong2 aA = *(const ulonglong2*)&As2[kk][ty*8];
            ulonglong2 aB = *(const ulonglong2*)&As2[kk][ty*8 + 4];
            ulonglong2 aC = *(const ulonglong2*)&As2[kk][128 + ty*8];
            ulonglong2 aD = *(const ulonglong2*)&As2[kk][128 + ty*8 + 4];
            ulonglong2 b01 = *(const ulonglong2*)&Bs[kk][tx*4];
            ulonglong2 b23 = *(const ulonglong2*)&Bs[kk][64 + tx*4];
            ull ad[8] = {aA.x, aA.y, aB.x, aB.y, aC.x, aC.y, aD.x, aD.y};
            ull bp[4] = {b01.x, b01.y, b23.x, b23.y};
#pragma unroll
            for (int i = 0; i < 8; i++)
#pragma unroll
                for (int j = 0; j < 4; j++)
                    acc[i][j] = ffma2(ad[i], bp[j], acc[i][j]);
        }
        __syncthreads();
        if (more) { a0 = na0; a1 = na1; b0 = nb0; b1 = nb1; }
    }

    // epilogue
#pragma unroll
    for (int i = 0; i < 8; i++) {
        const int row = rowBase + ((i < 4) ? (ty*4 + i) : (64 + ty*4 + (i - 4)));
        const int c0 = colBase + tx*4;
        const int c1 = colBase + 64 + tx*4;
        if (c0 < N) {
            float2 p0 = unpack2(acc[i][0]), p1 = unpack2(acc[i][1]);
            *(float4*)(C + (size_t)row * N + c0) = make_float4(p0.x, p0.y, p1.x, p1.y);
        }
        if (c1 < N) {
            float2 p2 = unpack2(acc[i][2]), p3 = unpack2(acc[i][3]);
            *(float4*)(C + (size_t)row * N + c1) = make_float4(p2.x, p2.y, p3.x, p3.y);
        }
    }
}

// ---------------- conv(4, causal, depthwise) + SiLU, plus dt/dA ----------------
__global__ void __launch_bounds__(256)
conv_dt_kernel(const float* __restrict__ conv_w, const float* __restrict__ conv_b,
               const float* __restrict__ dt_bias, const float* __restrict__ A_log)
{
    const int bl  = blockIdx.x;          // b*LSEQ + l
    const int l   = bl & (LSEQ - 1);
    const int tid = threadIdx.x;
    const float* base = g_zxbcdt + (size_t)bl * DPROJ + DIN;   // xBC raw at column 2048
    float* out = g_xc + (size_t)bl * CONVDIM;

    for (int c = tid; c < CONVDIM; c += 256) {
        const float4 w = *(const float4*)(conv_w + c * 4);
        float acc = conv_b[c];
        if (l >= 3) {
            acc += base[c - 3*DPROJ] * w.x + base[c - 2*DPROJ] * w.y
                 + base[c -   DPROJ] * w.z + base[c]            * w.w;
        } else {
            const float wk[4] = {w.x, w.y, w.z, w.w};
#pragma unroll
            for (int k = 0; k < 4; k++) {
                int ll = l + k - 3;
                if (ll >= 0) acc += base[c + (k - 3) * DPROJ] * wk[k];
            }
        }
        out[c] = acc / (1.f + expf(-acc));   // silu
    }

    if (tid < NH) {
        float v = g_zxbcdt[(size_t)bl * DPROJ + (DPROJ - NH) + tid] + dt_bias[tid];
        float dtv = (v > 20.f) ? v : log1pf(expf(v));
        g_dt[bl * NH + tid] = dtv;
        g_dA[bl * NH + tid] = expf(-expf(A_log[tid]) * dtv);
    }
}

// ---------------- selective scan: one CTA per (b,h) ----------------
// 256 threads: p = tid>>2 (0..63), nc = tid&3 (n-chunk of 32). State in regs as f32x2.
__global__ void __launch_bounds__(256)
scan_kernel(const float* __restrict__ Dv)
{
    const int h = blockIdx.x, b = blockIdx.y;
    const int tid = threadIdx.x;
    const int nc = tid & 3, p = tid >> 2;

    const float* xc  = g_xc + (size_t)b * LSEQ * CONVDIM;
    const float* dAp = g_dA + (size_t)b * LSEQ * NH + h;
    const float* dtp = g_dt + (size_t)b * LSEQ * NH + h;
    float* yout = g_y + (size_t)b * LSEQ * DIN + h * HD + p;

    // padded chunk stride 36 floats (144B): nc chunks start at banks 0/4/8/12 -> conflict-free
    __shared__ __align__(16) float sB[2][148];
    __shared__ __align__(16) float sC[2][148];
    __shared__ float sx[2][64];

    ull hs[16];
#pragma unroll
    for (int i = 0; i < 16; i++) hs[i] = 0ull;
    const float Dh = Dv[h];

    // preload l = 0
    {
        const float* row = xc;
        if (tid < 128) sB[0][(tid >> 5) * 36 + (tid & 31)] = row[DIN + tid];
        else { int t = tid - 128; sC[0][(t >> 5) * 36 + (t & 31)] = row[DIN + DSTATE + t]; }
        if (tid < 64) sx[0][tid] = row[h * HD + tid];
    }

    for (int l = 0; l < LSEQ; l++) {
        __syncthreads();
        const int buf = l & 1;
        if (l + 1 < LSEQ) {
            const float* row = xc + (size_t)(l + 1) * CONVDIM;
            const int nb = buf ^ 1;
            if (tid < 128) sB[nb][(tid >> 5) * 36 + (tid & 31)] = row[DIN + tid];
            else { int t = tid - 128; sC[nb][(t >> 5) * 36 + (t & 31)] = row[DIN + DSTATE + t]; }
            if (tid < 64) sx[nb][tid] = row[h * HD + tid];
        }
        const float dAv = __ldg(dAp + (size_t)l * NH);
        const float dtv = __ldg(dtp + (size_t)l * NH);
        const float xv  = sx[buf][p];
        const float sv  = dtv * xv;
        const ull dA2 = pack2(dAv, dAv);
        const ull s2  = pack2(sv, sv);

        const ulonglong2* B2 = (const ulonglong2*)(&sB[buf][nc * 36]);
        const ulonglong2* C2 = (const ulonglong2*)(&sC[buf][nc * 36]);
        ull acc0 = 0ull, acc1 = 0ull;
#pragma unroll
        for (int i = 0; i < 8; i++) {
            ulonglong2 bb = B2[i], cc = C2[i];
            hs[2*i]   = ffma2(dA2, hs[2*i],   fmul2(s2, bb.x));
            acc0      = ffma2(hs[2*i],   cc.x, acc0);
            hs[2*i+1] = ffma2(dA2, hs[2*i+1], fmul2(s2, bb.y));
            acc1      = ffma2(hs[2*i+1], cc.y, acc1);
        }
        float2 f0 = unpack2(acc0), f1 = unpack2(acc1);
        float r = (f0.x + f0.y) + (f1.x + f1.y);
        r += __shfl_xor_sync(0xffffffffu, r, 1);
        r += __shfl_xor_sync(0xffffffffu, r, 2);
        if (nc == 0) yout[(size_t)l * DIN] = r + Dh * xv;
    }
}

// ---------------- gating + RMSNorm (in place on g_y) ----------------
__global__ void __launch_bounds__(256)
gate_norm_kernel(const float* __restrict__ norm_w)
{
    const int bl = blockIdx.x;
    float* yrow = g_y + (size_t)bl * DIN;
    const float* zrow = g_zxbcdt + (size_t)bl * DPROJ;   // z at cols 0..2047
    const int tid = threadIdx.x;

    float v[8];
    float ss = 0.f;
#pragma unroll
    for (int j = 0; j < 8; j++) {
        const int c = tid + j * 256;
        const float z = zrow[c];
        const float val = yrow[c] * (z / (1.f + expf(-z)));
        v[j] = val;
        ss += val * val;
    }
#pragma unroll
    for (int o = 16; o; o >>= 1) ss += __shfl_xor_sync(0xffffffffu, ss, o);
    __shared__ float red[8];
    if ((tid & 31) == 0) red[tid >> 5] = ss;
    __syncthreads();
    float tot = 0.f;
#pragma unroll
    for (int i = 0; i < 8; i++) tot += red[i];
    const float scale = rsqrtf(tot * (1.f / (float)DIN) + 1e-5f);
#pragma unroll
    for (int j = 0; j < 8; j++) {
        const int c = tid + j * 256;
        yrow[c] = v[j] * scale * norm_w[c];
    }
}

// ---------------- launch ----------------
extern "C" void kernel_launch(void* const* d_in, const int* in_sizes, int n_in,
                              void* d_out, int out_size)
{
    (void)in_sizes; (void)n_in; (void)out_size;

    const float* hidden  = (const float*)d_in[0];
    const float* W_in    = (const float*)d_in[1];
    const float* conv_w  = (const float*)d_in[2];
    const float* conv_b  = (const float*)d_in[3];
    const float* dt_bias = (const float*)d_in[4];
    const float* A_log   = (const float*)d_in[5];
    const float* Dvec    = (const float*)d_in[6];
    const float* norm_w  = (const float*)d_in[7];
    const float* W_out   = (const float*)d_in[8];
    float* out = (float*)d_out;

    static float* zx = nullptr;
    static float* y  = nullptr;
    if (!zx) {
        void* p;
        cudaGetSymbolAddress(&p, g_zxbcdt); zx = (float*)p;
        cudaGetSymbolAddress(&p, g_y);      y  = (float*)p;
    }

    // 1) zxbcdt = hidden @ W_in : [8192,1024] x [1024,4384]
    sgemm_f32x2<<<dim3((DPROJ + 127) / 128, MROWS / 128), 256>>>(hidden, W_in, zx,
                                                                 MROWS, DPROJ, DMODEL);
    // 2) conv + silu + dt/dA
    conv_dt_kernel<<<MROWS, 256>>>(conv_w, conv_b, dt_bias, A_log);
    // 3) selective scan
    scan_kernel<<<dim3(NH, BB), 256>>>(Dvec);
    // 4) gating + rmsnorm (in place)
    gate_norm_kernel<<<MROWS, 256>>>(norm_w);
    // 5) out = y @ W_out : [8192,2048] x [2048,1024]
    sgemm_f32x2<<<dim3(DMODEL / 128, MROWS / 128), 256>>>(y, W_out, out,
                                                          MROWS, DMODEL, DIN);
}

// round 6
// speedup vs baseline: 1.7616x; 1.7616x over previous
#include <cuda_runtime.h>
#include <cuda_bf16.h>
#include <math.h>
#include <stdint.h>

// ---------------- problem constants ----------------
#define BB        4
#define LSEQ      2048
#define DMODEL    1024
#define DIN       2048          // D_INNER
#define NH        32            // NHEADS
#define HD        64            // HEADDIM
#define DSTATE    128
#define CONVDIM   2304          // DIN + 2*DSTATE
#define DPROJ     4384          // 2*DIN + 2*DSTATE + NH
#define MROWS     (BB*LSEQ)     // 8192

typedef unsigned long long ull;

// ---------------- scratch (static __device__, no allocs) ----------------
__device__ float g_zxbcdt[(size_t)MROWS * DPROJ];
__device__ float g_xc[(size_t)MROWS * CONVDIM];
__device__ float g_y[(size_t)MROWS * DIN];
__device__ float g_dt[(size_t)MROWS * NH];
__device__ float g_dA[(size_t)MROWS * NH];

// bf16 split operands
__device__ __nv_bfloat16 g_ahi[(size_t)MROWS * DMODEL];
__device__ __nv_bfloat16 g_alo[(size_t)MROWS * DMODEL];
__device__ __nv_bfloat16 g_w1hi[(size_t)DPROJ * DMODEL];  // W_in^T  [N][K]
__device__ __nv_bfloat16 g_w1lo[(size_t)DPROJ * DMODEL];
__device__ __nv_bfloat16 g_yhi[(size_t)MROWS * DIN];
__device__ __nv_bfloat16 g_ylo[(size_t)MROWS * DIN];
__device__ __nv_bfloat16 g_w2hi[(size_t)DMODEL * DIN];    // W_out^T [N][K]
__device__ __nv_bfloat16 g_w2lo[(size_t)DMODEL * DIN];

// ---------------- f32x2 helpers (scan kernel) ----------------
__device__ __forceinline__ ull ffma2(ull a, ull b, ull c) {
    ull d; asm("fma.rn.f32x2 %0, %1, %2, %3;" : "=l"(d) : "l"(a), "l"(b), "l"(c)); return d;
}
__device__ __forceinline__ ull fmul2(ull a, ull b) {
    ull d; asm("mul.rn.f32x2 %0, %1, %2;" : "=l"(d) : "l"(a), "l"(b)); return d;
}
__device__ __forceinline__ ull pack2(float lo, float hi) {
    ull r; asm("mov.b64 %0, {%1, %2};" : "=l"(r) : "f"(lo), "f"(hi)); return r;
}
__device__ __forceinline__ float2 unpack2(ull v) {
    float2 f; asm("mov.b64 {%0, %1}, %2;" : "=f"(f.x), "=f"(f.y) : "l"(v)); return f;
}

// ---------------- mma.sync / ldmatrix / cp.async helpers (plain sm_103 OK) ----
__device__ __forceinline__ uint32_t smem_u32(const void* p) {
    uint32_t a;
    asm("{ .reg .u64 t; cvta.to.shared.u64 t, %1; cvt.u32.u64 %0, t; }" : "=r"(a) : "l"(p));
    return a;
}
__device__ __forceinline__ void ldsm4(uint32_t& r0, uint32_t& r1, uint32_t& r2, uint32_t& r3,
                                      uint32_t addr) {
    asm volatile("ldmatrix.sync.aligned.m8n8.x4.shared.b16 {%0,%1,%2,%3}, [%4];"
                 : "=r"(r0), "=r"(r1), "=r"(r2), "=r"(r3) : "r"(addr));
}
__device__ __forceinline__ void mma16816(float* c, uint32_t a0, uint32_t a1, uint32_t a2,
                                         uint32_t a3, uint32_t b0, uint32_t b1) {
    asm volatile(
        "mma.sync.aligned.m16n8k16.row.col.f32.bf16.bf16.f32 "
        "{%0,%1,%2,%3}, {%4,%5,%6,%7}, {%8,%9}, {%0,%1,%2,%3};"
        : "+f"(c[0]), "+f"(c[1]), "+f"(c[2]), "+f"(c[3])
        : "r"(a0), "r"(a1), "r"(a2), "r"(a3), "r"(b0), "r"(b1));
}
__device__ __forceinline__ void cp16(uint32_t saddr, const void* gaddr, uint32_t srcbytes) {
    asm volatile("cp.async.cg.shared.global [%0], [%1], 16, %2;"
                 :: "r"(saddr), "l"(gaddr), "r"(srcbytes));
}
__device__ __forceinline__ void cp_commit() { asm volatile("cp.async.commit_group;"); }
template <int N_> __device__ __forceinline__ void cp_wait() {
    asm volatile("cp.async.wait_group %0;" :: "n"(N_));
}

// ---------------- split / transpose-split converters ----------------
__global__ void __launch_bounds__(256)
convert_split(const float* __restrict__ src, __nv_bfloat16* __restrict__ hi,
              __nv_bfloat16* __restrict__ lo, int n4)
{
    int i = blockIdx.x * 256 + threadIdx.x;
    if (i >= n4) return;
    float4 v = ((const float4*)src)[i];
    __nv_bfloat16 h0 = __float2bfloat16(v.x), h1 = __float2bfloat16(v.y);
    __nv_bfloat16 h2 = __float2bfloat16(v.z), h3 = __float2bfloat16(v.w);
    __nv_bfloat162 H0; H0.x = h0; H0.y = h1;
    __nv_bfloat162 H1; H1.x = h2; H1.y = h3;
    ((__nv_bfloat162*)hi)[i*2]   = H0;
    ((__nv_bfloat162*)hi)[i*2+1] = H1;
    __nv_bfloat162 L0, L1;
    L0.x = __float2bfloat16(v.x - __bfloat162float(h0));
    L0.y = __float2bfloat16(v.y - __bfloat162float(h1));
    L1.x = __float2bfloat16(v.z - __bfloat162float(h2));
    L1.y = __float2bfloat16(v.w - __bfloat162float(h3));
    ((__nv_bfloat162*)lo)[i*2]   = L0;
    ((__nv_bfloat162*)lo)[i*2+1] = L1;
}

// src [K][N] fp32 -> hiT/loT [N][K] bf16 split
__global__ void __launch_bounds__(256)
transpose_split(const float* __restrict__ src, __nv_bfloat16* __restrict__ hiT,
                __nv_bfloat16* __restrict__ loT, int K, int N)
{
    __shared__ float t[32][33];
    const int kb = blockIdx.y * 32, nb = blockIdx.x * 32;
    const int tx = threadIdx.x & 31, ty = threadIdx.x >> 5;
#pragma unroll
    for (int j = 0; j < 4; j++)
        t[ty + j*8][tx] = src[(size_t)(kb + ty + j*8) * N + nb + tx];
    __syncthreads();
#pragma unroll
    for (int j = 0; j < 4; j++) {
        const int n = nb + ty + j*8, k = kb + tx;
        const float v = t[tx][ty + j*8];
        const __nv_bfloat16 h = __float2bfloat16(v);
        hiT[(size_t)n * K + k] = h;
        loT[(size_t)n * K + k] = __float2bfloat16(v - __bfloat162float(h));
    }
}

// ---------------- HMMA GEMM: C[M,N] = (Ahi+Alo)[M,K] @ (Bhi+Blo)^T  (B given [N][K])
// CTA 128x128, BK=32, double-buffered cp.async, 8 warps (2x4), warp tile 64x32.
// bf16x3: hi*hi + hi*lo + lo*hi into fp32 accumulators.
#define GS_STRIDE 80            // bytes per smem row (40 bf16, conflict-free ldmatrix)
#define GS_TILE   (128 * GS_STRIDE)   // 10240 B
#define GS_BUF    (4 * GS_TILE)       // Ahi|Alo|Bhi|Blo = 40960 B
#define GS_DYN    (2 * GS_BUF)        // 81920 B

__global__ void __launch_bounds__(256)
gemm_hmma(const __nv_bfloat16* __restrict__ Ahi, const __nv_bfloat16* __restrict__ Alo,
          const __nv_bfloat16* __restrict__ BhiT, const __nv_bfloat16* __restrict__ BloT,
          float* __restrict__ C, int N, int K)
{
    extern __shared__ char smem[];
    const uint32_t sb = smem_u32(smem);

    const int tid = threadIdx.x;
    const int lane = tid & 31;
    const int wid = tid >> 5;
    const int warp_m = wid & 1;          // 0..1
    const int warp_n = wid >> 1;         // 0..3
    const int rowBase = blockIdx.y << 7;
    const int colBase = blockIdx.x << 7;
    const int nkc = K >> 5;

    float acc[4][4][4];
#pragma unroll
    for (int i = 0; i < 4; i++)
#pragma unroll
        for (int j = 0; j < 4; j++)
#pragma unroll
            for (int q = 0; q < 4; q++) acc[i][j][q] = 0.f;

    // ---- async tile loader: chunk kc -> buffer buf ----
    auto load_chunk = [&](int kc, int buf) {
        const uint32_t base = sb + (uint32_t)buf * GS_BUF;
        // A tiles (hi, lo): 128 rows x 32 bf16
#pragma unroll
        for (int it = 0; it < 2; it++) {
            const int id = tid + it * 256;           // 0..511
            const int row = id >> 2, c = id & 3;     // c: 16B chunk (8 bf16)
            const size_t g = (size_t)(rowBase + row) * K + kc * 32 + c * 8;
            const uint32_t so = (uint32_t)(row * GS_STRIDE + c * 16);
            cp16(base + so,            Ahi + g, 16);
            cp16(base + GS_TILE + so,  Alo + g, 16);
        }
        // B tiles (hi, lo): 128 N-rows x 32 bf16 (K-major), zero-fill past N
#pragma unroll
        for (int it = 0; it < 2; it++) {
            const int id = tid + it * 256;
            const int row = id >> 2, c = id & 3;
            const int n = colBase + row;
            const int nn = (n < N) ? n : 0;
            const uint32_t valid = (n < N) ? 16u : 0u;
            const size_t g = (size_t)nn * K + kc * 32 + c * 8;
            const uint32_t so = (uint32_t)(row * GS_STRIDE + c * 16);
            cp16(base + 2*GS_TILE + so, BhiT + g, valid);
            cp16(base + 3*GS_TILE + so, BloT + g, valid);
        }
    };

    load_chunk(0, 0);
    cp_commit();

    for (int kc = 0; kc < nkc; kc++) {
        const int buf = kc & 1;
        if (kc + 1 < nkc) {
            load_chunk(kc + 1, buf ^ 1);
            cp_commit();
            cp_wait<1>();
        } else {
            cp_wait<0>();
        }
        __syncthreads();

        const uint32_t base = sb + (uint32_t)buf * GS_BUF;
        const uint32_t aHb = base;
        const uint32_t aLb = base + GS_TILE;
        const uint32_t bHb = base + 2 * GS_TILE;
        const uint32_t bLb = base + 3 * GS_TILE;

#pragma unroll
        for (int ks = 0; ks < 2; ks++) {       // two k16 steps per chunk
            const int kb = ks * 16;
            // fragment byte offset within a tile for this lane:
            // row = tileRow + (lane&15), col16B = kb*2 + (lane>>4)*16
            const uint32_t loff = (uint32_t)((lane & 15) * GS_STRIDE + kb * 2 + (lane >> 4) * 16);

            uint32_t aH[4][4], aL[4][4];
#pragma unroll
            for (int mt = 0; mt < 4; mt++) {
                const uint32_t ro = (uint32_t)((warp_m * 64 + mt * 16) * GS_STRIDE) + loff;
                ldsm4(aH[mt][0], aH[mt][1], aH[mt][2], aH[mt][3], aHb + ro);
                ldsm4(aL[mt][0], aL[mt][1], aL[mt][2], aL[mt][3], aLb + ro);
            }
            uint32_t bH[4][2], bL[4][2];
#pragma unroll
            for (int np = 0; np < 2; np++) {
                const uint32_t ro = (uint32_t)((warp_n * 32 + np * 16) * GS_STRIDE) + loff;
                uint32_t r0, r1, r2, r3;
                ldsm4(r0, r1, r2, r3, bHb + ro);
                bH[np*2][0] = r0; bH[np*2][1] = r2;
                bH[np*2+1][0] = r1; bH[np*2+1][1] = r3;
                ldsm4(r0, r1, r2, r3, bLb + ro);
                bL[np*2][0] = r0; bL[np*2][1] = r2;
                bL[np*2+1][0] = r1; bL[np*2+1][1] = r3;
            }
#pragma unroll
            for (int mt = 0; mt < 4; mt++)
#pragma unroll
                for (int nt = 0; nt < 4; nt++) {
                    mma16816(acc[mt][nt], aH[mt][0], aH[mt][1], aH[mt][2], aH[mt][3],
                             bH[nt][0], bH[nt][1]);
                    mma16816(acc[mt][nt], aH[mt][0], aH[mt][1], aH[mt][2], aH[mt][3],
                             bL[nt][0], bL[nt][1]);
                    mma16816(acc[mt][nt], aL[mt][0], aL[mt][1], aL[mt][2], aL[mt][3],
                             bH[nt][0], bH[nt][1]);
                }
        }
        __syncthreads();
    }

    // epilogue: thread holds C[m+g][n+tg*2 +{0,1}] and row+8
    const int g = lane >> 2, tg = lane & 3;
#pragma unroll
    for (int mt = 0; mt < 4; mt++) {
#pragma unroll
        for (int nt = 0; nt < 4; nt++) {
            const int col = colBase + warp_n * 32 + nt * 8 + tg * 2;
            if (col < N) {
                const int r0 = rowBase + warp_m * 64 + mt * 16 + g;
                float2 v0 = make_float2(acc[mt][nt][0], acc[mt][nt][1]);
                float2 v1 = make_float2(acc[mt][nt][2], acc[mt][nt][3]);
                *(float2*)(C + (size_t)r0 * N + col)       = v0;
                *(float2*)(C + (size_t)(r0 + 8) * N + col) = v1;
            }
        }
    }
}

// ---------------- conv(4, causal, depthwise) + SiLU, plus dt/dA ----------------
__global__ void __launch_bounds__(256)
conv_dt_kernel(const float* __restrict__ conv_w, const float* __restrict__ conv_b,
               const float* __restrict__ dt_bias, const float* __restrict__ A_log)
{
    const int bl  = blockIdx.x;
    const int l   = bl & (LSEQ - 1);
    const int tid = threadIdx.x;
    const float* base = g_zxbcdt + (size_t)bl * DPROJ + DIN;
    float* out = g_xc + (size_t)bl * CONVDIM;

    for (int c = tid; c < CONVDIM; c += 256) {
        const float4 w = *(const float4*)(conv_w + c * 4);
        float acc = conv_b[c];
        if (l >= 3) {
            acc += base[c - 3*DPROJ] * w.x + base[c - 2*DPROJ] * w.y
                 + base[c -   DPROJ] * w.z + base[c]            * w.w;
        } else {
            const float wk[4] = {w.x, w.y, w.z, w.w};
#pragma unroll
            for (int k = 0; k < 4; k++) {
                int ll = l + k - 3;
                if (ll >= 0) acc += base[c + (k - 3) * DPROJ] * wk[k];
            }
        }
        out[c] = acc / (1.f + expf(-acc));
    }

    if (tid < NH) {
        float v = g_zxbcdt[(size_t)bl * DPROJ + (DPROJ - NH) + tid] + dt_bias[tid];
        float dtv = (v > 20.f) ? v : log1pf(expf(v));
        g_dt[bl * NH + tid] = dtv;
        g_dA[bl * NH + tid] = expf(-expf(A_log[tid]) * dtv);
    }
}

// ---------------- selective scan: one CTA per (b,h) ----------------
__global__ void __launch_bounds__(256)
scan_kernel(const float* __restrict__ Dv)
{
    const int h = blockIdx.x, b = blockIdx.y;
    const int tid = threadIdx.x;
    const int nc = tid & 3, p = tid >> 2;

    const float* xc  = g_xc + (size_t)b * LSEQ * CONVDIM;
    const float* dAp = g_dA + (size_t)b * LSEQ * NH + h;
    const float* dtp = g_dt + (size_t)b * LSEQ * NH + h;
    float* yout = g_y + (size_t)b * LSEQ * DIN + h * HD + p;

    __shared__ __align__(16) float sB[2][148];
    __shared__ __align__(16) float sC[2][148];
    __shared__ float sx[2][64];

    ull hs[16];
#pragma unroll
    for (int i = 0; i < 16; i++) hs[i] = 0ull;
    const float Dh = Dv[h];

    {
        const float* row = xc;
        if (tid < 128) sB[0][(tid >> 5) * 36 + (tid & 31)] = row[DIN + tid];
        else { int t = tid - 128; sC[0][(t >> 5) * 36 + (t & 31)] = row[DIN + DSTATE + t]; }
        if (tid < 64) sx[0][tid] = row[h * HD + tid];
    }

    for (int l = 0; l < LSEQ; l++) {
        __syncthreads();
        const int buf = l & 1;
        if (l + 1 < LSEQ) {
            const float* row = xc + (size_t)(l + 1) * CONVDIM;
            const int nb = buf ^ 1;
            if (tid < 128) sB[nb][(tid >> 5) * 36 + (tid & 31)] = row[DIN + tid];
            else { int t = tid - 128; sC[nb][(t >> 5) * 36 + (t & 31)] = row[DIN + DSTATE + t]; }
            if (tid < 64) sx[nb][tid] = row[h * HD + tid];
        }
        const float dAv = __ldg(dAp + (size_t)l * NH);
        const float dtv = __ldg(dtp + (size_t)l * NH);
        const float xv  = sx[buf][p];
        const float sv  = dtv * xv;
        const ull dA2 = pack2(dAv, dAv);
        const ull s2  = pack2(sv, sv);

        const ulonglong2* B2 = (const ulonglong2*)(&sB[buf][nc * 36]);
        const ulonglong2* C2 = (const ulonglong2*)(&sC[buf][nc * 36]);
        ull acc0 = 0ull, acc1 = 0ull;
#pragma unroll
        for (int i = 0; i < 8; i++) {
            ulonglong2 bb = B2[i], cc = C2[i];
            hs[2*i]   = ffma2(dA2, hs[2*i],   fmul2(s2, bb.x));
            acc0      = ffma2(hs[2*i],   cc.x, acc0);
            hs[2*i+1] = ffma2(dA2, hs[2*i+1], fmul2(s2, bb.y));
            acc1      = ffma2(hs[2*i+1], cc.y, acc1);
        }
        float2 f0 = unpack2(acc0), f1 = unpack2(acc1);
        float r = (f0.x + f0.y) + (f1.x + f1.y);
        r += __shfl_xor_sync(0xffffffffu, r, 1);
        r += __shfl_xor_sync(0xffffffffu, r, 2);
        if (nc == 0) yout[(size_t)l * DIN] = r + Dh * xv;
    }
}

// ---------------- gating + RMSNorm -> bf16 hi/lo split ----------------
__global__ void __launch_bounds__(256)
gate_norm_kernel(const float* __restrict__ norm_w)
{
    const int bl = blockIdx.x;
    const float* yrow = g_y + (size_t)bl * DIN;
    const float* zrow = g_zxbcdt + (size_t)bl * DPROJ;
    __nv_bfloat16* hrow = g_yhi + (size_t)bl * DIN;
    __nv_bfloat16* lrow = g_ylo + (size_t)bl * DIN;
    const int tid = threadIdx.x;

    float v[8];
    float ss = 0.f;
#pragma unroll
    for (int j = 0; j < 8; j++) {
        const int c = tid + j * 256;
        const float z = zrow[c];
        const float val = yrow[c] * (z / (1.f + expf(-z)));
        v[j] = val;
        ss += val * val;
    }
#pragma unroll
    for (int o = 16; o; o >>= 1) ss += __shfl_xor_sync(0xffffffffu, ss, o);
    __shared__ float red[8];
    if ((tid & 31) == 0) red[tid >> 5] = ss;
    __syncthreads();
    float tot = 0.f;
#pragma unroll
    for (int i = 0; i < 8; i++) tot += red[i];
    const float scale = rsqrtf(tot * (1.f / (float)DIN) + 1e-5f);
#pragma unroll
    for (int j = 0; j < 8; j++) {
        const int c = tid + j * 256;
        const float o = v[j] * scale * norm_w[c];
        const __nv_bfloat16 hh = __float2bfloat16(o);
        hrow[c] = hh;
        lrow[c] = __float2bfloat16(o - __bfloat162float(hh));
    }
}

// ---------------- launch ----------------
extern "C" void kernel_launch(void* const* d_in, const int* in_sizes, int n_in,
                              void* d_out, int out_size)
{
    (void)in_sizes; (void)n_in; (void)out_size;

    const float* hidden  = (const float*)d_in[0];
    const float* W_in    = (const float*)d_in[1];
    const float* conv_w  = (const float*)d_in[2];
    const float* conv_b  = (const float*)d_in[3];
    const float* dt_bias = (const float*)d_in[4];
    const float* A_log   = (const float*)d_in[5];
    const float* Dvec    = (const float*)d_in[6];
    const float* norm_w  = (const float*)d_in[7];
    const float* W_out   = (const float*)d_in[8];
    float* out = (float*)d_out;

    static float* zx = nullptr;
    static __nv_bfloat16 *ahi, *alo, *w1hi, *w1lo, *yhi, *ylo, *w2hi, *w2lo;
    if (!zx) {
        void* p;
        cudaGetSymbolAddress(&p, g_zxbcdt); zx  = (float*)p;
        cudaGetSymbolAddress(&p, g_ahi);  ahi  = (__nv_bfloat16*)p;
        cudaGetSymbolAddress(&p, g_alo);  alo  = (__nv_bfloat16*)p;
        cudaGetSymbolAddress(&p, g_w1hi); w1hi = (__nv_bfloat16*)p;
        cudaGetSymbolAddress(&p, g_w1lo); w1lo = (__nv_bfloat16*)p;
        cudaGetSymbolAddress(&p, g_yhi);  yhi  = (__nv_bfloat16*)p;
        cudaGetSymbolAddress(&p, g_ylo);  ylo  = (__nv_bfloat16*)p;
        cudaGetSymbolAddress(&p, g_w2hi); w2hi = (__nv_bfloat16*)p;
        cudaGetSymbolAddress(&p, g_w2lo); w2lo = (__nv_bfloat16*)p;
        cudaFuncSetAttribute(gemm_hmma, cudaFuncAttributeMaxDynamicSharedMemorySize, GS_DYN);
    }

    // 0) operand prep
    {
        const int n4 = MROWS * DMODEL / 4;
        convert_split<<<(n4 + 255) / 256, 256>>>(hidden, ahi, alo, n4);
    }
    transpose_split<<<dim3(DPROJ / 32, DMODEL / 32), 256>>>(W_in, w1hi, w1lo, DMODEL, DPROJ);
    transpose_split<<<dim3(DMODEL / 32, DIN / 32), 256>>>(W_out, w2hi, w2lo, DIN, DMODEL);

    // 1) zxbcdt = hidden @ W_in : [8192,1024] x [1024,4384]   (HMMA bf16x3)
    gemm_hmma<<<dim3((DPROJ + 127) / 128, MROWS / 128), 256, GS_DYN>>>(
        ahi, alo, w1hi, w1lo, zx, DPROJ, DMODEL);

    // 2) conv + silu + dt/dA
    conv_dt_kernel<<<MROWS, 256>>>(conv_w, conv_b, dt_bias, A_log);

    // 3) selective scan
    scan_kernel<<<dim3(NH, BB), 256>>>(Dvec);

    // 4) gating + rmsnorm -> bf16 hi/lo
    gate_norm_kernel<<<MROWS, 256>>>(norm_w);

    // 5) out = y @ W_out : [8192,2048] x [2048,1024]          (HMMA bf16x3)
    gemm_hmma<<<dim3(DMODEL / 128, MROWS / 128), 256, GS_DYN>>>(
        yhi, ylo, w2hi, w2lo, out, DMODEL, DIN);
}

// round 7
// speedup vs baseline: 2.6112x; 1.4823x over previous
#include <cuda_runtime.h>
#include <cuda_bf16.h>
#include <math.h>
#include <stdint.h>

// ---------------- problem constants ----------------
#define BB        4
#define LSEQ      2048
#define DMODEL    1024
#define DIN       2048          // D_INNER
#define NH        32            // NHEADS
#define HD        64            // HEADDIM
#define DSTATE    128
#define CONVDIM   2304          // DIN + 2*DSTATE
#define DPROJ     4384          // 2*DIN + 2*DSTATE + NH
#define MROWS     (BB*LSEQ)     // 8192

typedef unsigned long long ull;

// ---------------- scratch (static __device__, no allocs) ----------------
__device__ float g_zxbcdt[(size_t)MROWS * DPROJ];
__device__ float g_xc[(size_t)MROWS * CONVDIM];
__device__ float g_y[(size_t)MROWS * DIN];
__device__ float g_dt[(size_t)MROWS * NH];
__device__ float g_dA[(size_t)MROWS * NH];

// bf16 split operands
__device__ __nv_bfloat16 g_ahi[(size_t)MROWS * DMODEL];
__device__ __nv_bfloat16 g_alo[(size_t)MROWS * DMODEL];
__device__ __nv_bfloat16 g_w1hi[(size_t)DPROJ * DMODEL];  // W_in^T  [N][K]
__device__ __nv_bfloat16 g_w1lo[(size_t)DPROJ * DMODEL];
__device__ __nv_bfloat16 g_yhi[(size_t)MROWS * DIN];
__device__ __nv_bfloat16 g_ylo[(size_t)MROWS * DIN];
__device__ __nv_bfloat16 g_w2hi[(size_t)DMODEL * DIN];    // W_out^T [N][K]
__device__ __nv_bfloat16 g_w2lo[(size_t)DMODEL * DIN];

// ---------------- f32x2 helpers ----------------
__device__ __forceinline__ ull ffma2(ull a, ull b, ull c) {
    ull d; asm("fma.rn.f32x2 %0, %1, %2, %3;" : "=l"(d) : "l"(a), "l"(b), "l"(c)); return d;
}
__device__ __forceinline__ ull fmul2(ull a, ull b) {
    ull d; asm("mul.rn.f32x2 %0, %1, %2;" : "=l"(d) : "l"(a), "l"(b)); return d;
}
__device__ __forceinline__ ull pack2(float lo, float hi) {
    ull r; asm("mov.b64 %0, {%1, %2};" : "=l"(r) : "f"(lo), "f"(hi)); return r;
}
__device__ __forceinline__ float2 unpack2(ull v) {
    float2 f; asm("mov.b64 {%0, %1}, %2;" : "=f"(f.x), "=f"(f.y) : "l"(v)); return f;
}

// ---------------- mma.sync / ldmatrix / cp.async helpers ----------------
__device__ __forceinline__ uint32_t smem_u32(const void* p) {
    uint32_t a;
    asm("{ .reg .u64 t; cvta.to.shared.u64 t, %1; cvt.u32.u64 %0, t; }" : "=r"(a) : "l"(p));
    return a;
}
__device__ __forceinline__ void ldsm4(uint32_t& r0, uint32_t& r1, uint32_t& r2, uint32_t& r3,
                                      uint32_t addr) {
    asm volatile("ldmatrix.sync.aligned.m8n8.x4.shared.b16 {%0,%1,%2,%3}, [%4];"
                 : "=r"(r0), "=r"(r1), "=r"(r2), "=r"(r3) : "r"(addr));
}
__device__ __forceinline__ void mma16816(float* c, uint32_t a0, uint32_t a1, uint32_t a2,
                                         uint32_t a3, uint32_t b0, uint32_t b1) {
    asm volatile(
        "mma.sync.aligned.m16n8k16.row.col.f32.bf16.bf16.f32 "
        "{%0,%1,%2,%3}, {%4,%5,%6,%7}, {%8,%9}, {%0,%1,%2,%3};"
        : "+f"(c[0]), "+f"(c[1]), "+f"(c[2]), "+f"(c[3])
        : "r"(a0), "r"(a1), "r"(a2), "r"(a3), "r"(b0), "r"(b1));
}
__device__ __forceinline__ void cp16(uint32_t saddr, const void* gaddr, uint32_t srcbytes) {
    asm volatile("cp.async.cg.shared.global [%0], [%1], 16, %2;"
                 :: "r"(saddr), "l"(gaddr), "r"(srcbytes));
}
__device__ __forceinline__ void cp4(uint32_t saddr, const void* gaddr) {
    asm volatile("cp.async.ca.shared.global [%0], [%1], 4;"
                 :: "r"(saddr), "l"(gaddr));
}
__device__ __forceinline__ void cp_commit() { asm volatile("cp.async.commit_group;"); }
template <int N_> __device__ __forceinline__ void cp_wait() {
    asm volatile("cp.async.wait_group %0;" :: "n"(N_));
}

// ---------------- split / transpose-split converters ----------------
__global__ void __launch_bounds__(256)
convert_split(const float* __restrict__ src, __nv_bfloat16* __restrict__ hi,
              __nv_bfloat16* __restrict__ lo, int n4)
{
    int i = blockIdx.x * 256 + threadIdx.x;
    if (i >= n4) return;
    float4 v = ((const float4*)src)[i];
    __nv_bfloat16 h0 = __float2bfloat16(v.x), h1 = __float2bfloat16(v.y);
    __nv_bfloat16 h2 = __float2bfloat16(v.z), h3 = __float2bfloat16(v.w);
    __nv_bfloat162 H0; H0.x = h0; H0.y = h1;
    __nv_bfloat162 H1; H1.x = h2; H1.y = h3;
    ((__nv_bfloat162*)hi)[i*2]   = H0;
    ((__nv_bfloat162*)hi)[i*2+1] = H1;
    __nv_bfloat162 L0, L1;
    L0.x = __float2bfloat16(v.x - __bfloat162float(h0));
    L0.y = __float2bfloat16(v.y - __bfloat162float(h1));
    L1.x = __float2bfloat16(v.z - __bfloat162float(h2));
    L1.y = __float2bfloat16(v.w - __bfloat162float(h3));
    ((__nv_bfloat162*)lo)[i*2]   = L0;
    ((__nv_bfloat162*)lo)[i*2+1] = L1;
}

// src [K][N] fp32 -> hiT/loT [N][K] bf16 split
__global__ void __launch_bounds__(256)
transpose_split(const float* __restrict__ src, __nv_bfloat16* __restrict__ hiT,
                __nv_bfloat16* __restrict__ loT, int K, int N)
{
    __shared__ float t[32][33];
    const int kb = blockIdx.y * 32, nb = blockIdx.x * 32;
    const int tx = threadIdx.x & 31, ty = threadIdx.x >> 5;
#pragma unroll
    for (int j = 0; j < 4; j++)
        t[ty + j*8][tx] = src[(size_t)(kb + ty + j*8) * N + nb + tx];
    __syncthreads();
#pragma unroll
    for (int j = 0; j < 4; j++) {
        const int n = nb + ty + j*8, k = kb + tx;
        const float v = t[tx][ty + j*8];
        const __nv_bfloat16 h = __float2bfloat16(v);
        hiT[(size_t)n * K + k] = h;
        loT[(size_t)n * K + k] = __float2bfloat16(v - __bfloat162float(h));
    }
}

// ---------------- HMMA GEMM (unchanged from R6 — measured 682us/GEMM1) -------
#define GS_STRIDE 80
#define GS_TILE   (128 * GS_STRIDE)
#define GS_BUF    (4 * GS_TILE)
#define GS_DYN    (2 * GS_BUF)

__global__ void __launch_bounds__(256)
gemm_hmma(const __nv_bfloat16* __restrict__ Ahi, const __nv_bfloat16* __restrict__ Alo,
          const __nv_bfloat16* __restrict__ BhiT, const __nv_bfloat16* __restrict__ BloT,
          float* __restrict__ C, int N, int K)
{
    extern __shared__ char smem[];
    const uint32_t sb = smem_u32(smem);

    const int tid = threadIdx.x;
    const int lane = tid & 31;
    const int wid = tid >> 5;
    const int warp_m = wid & 1;
    const int warp_n = wid >> 1;
    const int rowBase = blockIdx.y << 7;
    const int colBase = blockIdx.x << 7;
    const int nkc = K >> 5;

    float acc[4][4][4];
#pragma unroll
    for (int i = 0; i < 4; i++)
#pragma unroll
        for (int j = 0; j < 4; j++)
#pragma unroll
            for (int q = 0; q < 4; q++) acc[i][j][q] = 0.f;

    auto load_chunk = [&](int kc, int buf) {
        const uint32_t base = sb + (uint32_t)buf * GS_BUF;
#pragma unroll
        for (int it = 0; it < 2; it++) {
            const int id = tid + it * 256;
            const int row = id >> 2, c = id & 3;
            const size_t g = (size_t)(rowBase + row) * K + kc * 32 + c * 8;
            const uint32_t so = (uint32_t)(row * GS_STRIDE + c * 16);
            cp16(base + so,            Ahi + g, 16);
            cp16(base + GS_TILE + so,  Alo + g, 16);
        }
#pragma unroll
        for (int it = 0; it < 2; it++) {
            const int id = tid + it * 256;
            const int row = id >> 2, c = id & 3;
            const int n = colBase + row;
            const int nn = (n < N) ? n : 0;
            const uint32_t valid = (n < N) ? 16u : 0u;
            const size_t g = (size_t)nn * K + kc * 32 + c * 8;
            const uint32_t so = (uint32_t)(row * GS_STRIDE + c * 16);
            cp16(base + 2*GS_TILE + so, BhiT + g, valid);
            cp16(base + 3*GS_TILE + so, BloT + g, valid);
        }
    };

    load_chunk(0, 0);
    cp_commit();

    for (int kc = 0; kc < nkc; kc++) {
        const int buf = kc & 1;
        if (kc + 1 < nkc) {
            load_chunk(kc + 1, buf ^ 1);
            cp_commit();
            cp_wait<1>();
        } else {
            cp_wait<0>();
        }
        __syncthreads();

        const uint32_t base = sb + (uint32_t)buf * GS_BUF;
        const uint32_t aHb = base;
        const uint32_t aLb = base + GS_TILE;
        const uint32_t bHb = base + 2 * GS_TILE;
        const uint32_t bLb = base + 3 * GS_TILE;

#pragma unroll
        for (int ks = 0; ks < 2; ks++) {
            const int kb = ks * 16;
            const uint32_t loff = (uint32_t)((lane & 15) * GS_STRIDE + kb * 2 + (lane >> 4) * 16);

            uint32_t aH[4][4], aL[4][4];
#pragma unroll
            for (int mt = 0; mt < 4; mt++) {
                const uint32_t ro = (uint32_t)((warp_m * 64 + mt * 16) * GS_STRIDE) + loff;
                ldsm4(aH[mt][0], aH[mt][1], aH[mt][2], aH[mt][3], aHb + ro);
                ldsm4(aL[mt][0], aL[mt][1], aL[mt][2], aL[mt][3], aLb + ro);
            }
            uint32_t bH[4][2], bL[4][2];
#pragma unroll
            for (int np = 0; np < 2; np++) {
                const uint32_t ro = (uint32_t)((warp_n * 32 + np * 16) * GS_STRIDE) + loff;
                uint32_t r0, r1, r2, r3;
                ldsm4(r0, r1, r2, r3, bHb + ro);
                bH[np*2][0] = r0; bH[np*2][1] = r2;
                bH[np*2+1][0] = r1; bH[np*2+1][1] = r3;
                ldsm4(r0, r1, r2, r3, bLb + ro);
                bL[np*2][0] = r0; bL[np*2][1] = r2;
                bL[np*2+1][0] = r1; bL[np*2+1][1] = r3;
            }
#pragma unroll
            for (int mt = 0; mt < 4; mt++)
#pragma unroll
                for (int nt = 0; nt < 4; nt++) {
                    mma16816(acc[mt][nt], aH[mt][0], aH[mt][1], aH[mt][2], aH[mt][3],
                             bH[nt][0], bH[nt][1]);
                    mma16816(acc[mt][nt], aH[mt][0], aH[mt][1], aH[mt][2], aH[mt][3],
                             bL[nt][0], bL[nt][1]);
                    mma16816(acc[mt][nt], aL[mt][0], aL[mt][1], aL[mt][2], aL[mt][3],
                             bH[nt][0], bH[nt][1]);
                }
        }
        __syncthreads();
    }

    const int g = lane >> 2, tg = lane & 3;
#pragma unroll
    for (int mt = 0; mt < 4; mt++) {
#pragma unroll
        for (int nt = 0; nt < 4; nt++) {
            const int col = colBase + warp_n * 32 + nt * 8 + tg * 2;
            if (col < N) {
                const int r0 = rowBase + warp_m * 64 + mt * 16 + g;
                float2 v0 = make_float2(acc[mt][nt][0], acc[mt][nt][1]);
                float2 v1 = make_float2(acc[mt][nt][2], acc[mt][nt][3]);
                *(float2*)(C + (size_t)r0 * N + col)       = v0;
                *(float2*)(C + (size_t)(r0 + 8) * N + col) = v1;
            }
        }
    }
}

// ---------------- conv(4) + SiLU: 8 timesteps per CTA (sliding window) -------
__global__ void __launch_bounds__(256)
conv_kernel(const float* __restrict__ conv_w, const float* __restrict__ conv_b)
{
    const int bl0 = blockIdx.x * 8;            // first row of this CTA's 8
    const int l0  = bl0 & (LSEQ - 1);          // 8 steps never cross a batch edge
    const int tid = threadIdx.x;
    const float* base = g_zxbcdt + (size_t)bl0 * DPROJ + DIN;
    float* out = g_xc + (size_t)bl0 * CONVDIM;

    for (int c = tid; c < CONVDIM; c += 256) {
        const float4 w = *(const float4*)(conv_w + c * 4);
        const float bias = conv_b[c];
        float v[11];
#pragma unroll
        for (int k = 0; k < 11; k++) {
            const int ll = l0 + k - 3;
            v[k] = (ll >= 0) ? base[(ptrdiff_t)(k - 3) * DPROJ + c] : 0.f;
        }
#pragma unroll
        for (int j = 0; j < 8; j++) {
            const float a = bias + w.x * v[j] + w.y * v[j+1] + w.z * v[j+2] + w.w * v[j+3];
            out[(size_t)j * CONVDIM + c] = a / (1.f + expf(-a));
        }
    }
}

// ---------------- dt / dA ----------------
__global__ void __launch_bounds__(256)
dt_kernel(const float* __restrict__ dt_bias, const float* __restrict__ A_log)
{
    const int idx = blockIdx.x * 256 + threadIdx.x;   // MROWS*NH total
    const int bl = idx >> 5, hh = idx & 31;
    const float v = g_zxbcdt[(size_t)bl * DPROJ + (DPROJ - NH) + hh] + dt_bias[hh];
    const float dtv = (v > 20.f) ? v : log1pf(expf(v));
    g_dt[idx] = dtv;
    g_dA[idx] = expf(-expf(A_log[hh]) * dtv);
}

// ---------------- selective scan: cp.async 4-stage x 2-timestep pipeline -----
#define SC_STAGES 4
__global__ void __launch_bounds__(256)
scan_kernel(const float* __restrict__ Dv)
{
    const int h = blockIdx.x, b = blockIdx.y;
    const int tid = threadIdx.x;
    const int nc = tid & 3, p = tid >> 2;

    const float* xc  = g_xc + (size_t)b * LSEQ * CONVDIM;
    const float* dAp = g_dA + (size_t)b * LSEQ * NH + h;
    const float* dtp = g_dt + (size_t)b * LSEQ * NH + h;
    float* yout = g_y + (size_t)b * LSEQ * DIN + h * HD + p;

    // per (stage, sub-step): B/C padded to 148 floats (chunks at 0/36/72/108)
    __shared__ __align__(16) float sB[SC_STAGES][2][148];
    __shared__ __align__(16) float sC[SC_STAGES][2][148];
    __shared__ __align__(16) float sx[SC_STAGES][2][64];
    __shared__ float sdA[SC_STAGES][2];
    __shared__ float sdt[SC_STAGES][2];

    // stage loader: fill slot with timesteps l0, l0+1 (164 active threads)
    auto load_stage = [&](int slot, int l0) {
        if (tid < 160) {
            const int j = tid / 80, op = tid % 80;
            const float* row = xc + (size_t)(l0 + j) * CONVDIM;
            if (op < 64) {
                const int isC = op >> 5, o = op & 31;
                const int chunk = o >> 3, w = o & 7;
                const float* src = row + DIN + isC * DSTATE + chunk * 32 + w * 4;
                float* dstf = (isC ? &sC[slot][j][0] : &sB[slot][j][0]) + chunk * 36 + w * 4;
                cp16(smem_u32(dstf), src, 16);
            } else {
                const int o = op - 64;
                cp16(smem_u32(&sx[slot][j][o * 4]), row + h * HD + o * 4, 16);
            }
        } else if (tid < 164) {
            const int t = tid - 160, j = t >> 1;
            if (t & 1) cp4(smem_u32(&sdt[slot][j]), dtp + (size_t)(l0 + j) * NH);
            else       cp4(smem_u32(&sdA[slot][j]), dAp + (size_t)(l0 + j) * NH);
        }
    };

    ull hs[16];
#pragma unroll
    for (int i = 0; i < 16; i++) hs[i] = 0ull;
    const float Dh = Dv[h];

#pragma unroll
    for (int s = 0; s < SC_STAGES; s++) { load_stage(s, 2 * s); cp_commit(); }

    const int npairs = LSEQ / 2;
    for (int it = 0; it < npairs; it++) {
        const int slot = it & (SC_STAGES - 1);
        cp_wait<SC_STAGES - 1>();
        __syncthreads();

#pragma unroll
        for (int j = 0; j < 2; j++) {
            const float dAv = sdA[slot][j];
            const float dtv = sdt[slot][j];
            const float xv  = sx[slot][j][p];
            const float sv  = dtv * xv;
            const ull dA2 = pack2(dAv, dAv);
            const ull s2  = pack2(sv, sv);

            const ulonglong2* B2 = (const ulonglong2*)(&sB[slot][j][nc * 36]);
            const ulonglong2* C2 = (const ulonglong2*)(&sC[slot][j][nc * 36]);
            ull acc0 = 0ull, acc1 = 0ull;
#pragma unroll
            for (int i = 0; i < 8; i++) {
                ulonglong2 bb = B2[i], cc = C2[i];
                hs[2*i]   = ffma2(dA2, hs[2*i],   fmul2(s2, bb.x));
                acc0      = ffma2(hs[2*i],   cc.x, acc0);
                hs[2*i+1] = ffma2(dA2, hs[2*i+1], fmul2(s2, bb.y));
                acc1      = ffma2(hs[2*i+1], cc.y, acc1);
            }
            float2 f0 = unpack2(acc0), f1 = unpack2(acc1);
            float r = (f0.x + f0.y) + (f1.x + f1.y);
            r += __shfl_xor_sync(0xffffffffu, r, 1);
            r += __shfl_xor_sync(0xffffffffu, r, 2);
            if (nc == 0) yout[(size_t)(2 * it + j) * DIN] = r + Dh * xv;
        }
        __syncthreads();
        if (it + SC_STAGES < npairs) load_stage(slot, 2 * (it + SC_STAGES));
        cp_commit();
    }
}

// ---------------- gating + RMSNorm -> bf16 hi/lo split ----------------
__global__ void __launch_bounds__(256)
gate_norm_kernel(const float* __restrict__ norm_w)
{
    const int bl = blockIdx.x;
    const float* yrow = g_y + (size_t)bl * DIN;
    const float* zrow = g_zxbcdt + (size_t)bl * DPROJ;
    __nv_bfloat16* hrow = g_yhi + (size_t)bl * DIN;
    __nv_bfloat16* lrow = g_ylo + (size_t)bl * DIN;
    const int tid = threadIdx.x;

    float v[8];
    float ss = 0.f;
#pragma unroll
    for (int j = 0; j < 8; j++) {
        const int c = tid + j * 256;
        const float z = zrow[c];
        const float val = yrow[c] * (z / (1.f + expf(-z)));
        v[j] = val;
        ss += val * val;
    }
#pragma unroll
    for (int o = 16; o; o >>= 1) ss += __shfl_xor_sync(0xffffffffu, ss, o);
    __shared__ float red[8];
    if ((tid & 31) == 0) red[tid >> 5] = ss;
    __syncthreads();
    float tot = 0.f;
#pragma unroll
    for (int i = 0; i < 8; i++) tot += red[i];
    const float scale = rsqrtf(tot * (1.f / (float)DIN) + 1e-5f);
#pragma unroll
    for (int j = 0; j < 8; j++) {
        const int c = tid + j * 256;
        const float o = v[j] * scale * norm_w[c];
        const __nv_bfloat16 hh = __float2bfloat16(o);
        hrow[c] = hh;
        lrow[c] = __float2bfloat16(o - __bfloat162float(hh));
    }
}

// ---------------- launch ----------------
extern "C" void kernel_launch(void* const* d_in, const int* in_sizes, int n_in,
                              void* d_out, int out_size)
{
    (void)in_sizes; (void)n_in; (void)out_size;

    const float* hidden  = (const float*)d_in[0];
    const float* W_in    = (const float*)d_in[1];
    const float* conv_w  = (const float*)d_in[2];
    const float* conv_b  = (const float*)d_in[3];
    const float* dt_bias = (const float*)d_in[4];
    const float* A_log   = (const float*)d_in[5];
    const float* Dvec    = (const float*)d_in[6];
    const float* norm_w  = (const float*)d_in[7];
    const float* W_out   = (const float*)d_in[8];
    float* out = (float*)d_out;

    static float* zx = nullptr;
    static __nv_bfloat16 *ahi, *alo, *w1hi, *w1lo, *yhi, *ylo, *w2hi, *w2lo;
    if (!zx) {
        void* p;
        cudaGetSymbolAddress(&p, g_zxbcdt); zx  = (float*)p;
        cudaGetSymbolAddress(&p, g_ahi);  ahi  = (__nv_bfloat16*)p;
        cudaGetSymbolAddress(&p, g_alo);  alo  = (__nv_bfloat16*)p;
        cudaGetSymbolAddress(&p, g_w1hi); w1hi = (__nv_bfloat16*)p;
        cudaGetSymbolAddress(&p, g_w1lo); w1lo = (__nv_bfloat16*)p;
        cudaGetSymbolAddress(&p, g_yhi);  yhi  = (__nv_bfloat16*)p;
        cudaGetSymbolAddress(&p, g_ylo);  ylo  = (__nv_bfloat16*)p;
        cudaGetSymbolAddress(&p, g_w2hi); w2hi = (__nv_bfloat16*)p;
        cudaGetSymbolAddress(&p, g_w2lo); w2lo = (__nv_bfloat16*)p;
        cudaFuncSetAttribute(gemm_hmma, cudaFuncAttributeMaxDynamicSharedMemorySize, GS_DYN);
    }

    // 0) operand prep
    {
        const int n4 = MROWS * DMODEL / 4;
        convert_split<<<(n4 + 255) / 256, 256>>>(hidden, ahi, alo, n4);
    }
    transpose_split<<<dim3(DPROJ / 32, DMODEL / 32), 256>>>(W_in, w1hi, w1lo, DMODEL, DPROJ);
    transpose_split<<<dim3(DMODEL / 32, DIN / 32), 256>>>(W_out, w2hi, w2lo, DIN, DMODEL);

    // 1) zxbcdt = hidden @ W_in
    gemm_hmma<<<dim3((DPROJ + 127) / 128, MROWS / 128), 256, GS_DYN>>>(
        ahi, alo, w1hi, w1lo, zx, DPROJ, DMODEL);

    // 2) conv + silu (8 steps/CTA) and dt/dA
    conv_kernel<<<MROWS / 8, 256>>>(conv_w, conv_b);
    dt_kernel<<<MROWS * NH / 256, 256>>>(dt_bias, A_log);

    // 3) selective scan (cp.async pipelined)
    scan_kernel<<<dim3(NH, BB), 256>>>(Dvec);

    // 4) gating + rmsnorm -> bf16 hi/lo
    gate_norm_kernel<<<MROWS, 256>>>(norm_w);

    // 5) out = y @ W_out
    gemm_hmma<<<dim3(DMODEL / 128, MROWS / 128), 256, GS_DYN>>>(
        yhi, ylo, w2hi, w2lo, out, DMODEL, DIN);
}

// round 8
// speedup vs baseline: 2.6777x; 1.0255x over previous
#include <cuda_runtime.h>
#include <cuda_bf16.h>
#include <math.h>
#include <stdint.h>

// ---------------- problem constants ----------------
#define BB        4
#define LSEQ      2048
#define DMODEL    1024
#define DIN       2048          // D_INNER
#define NH        32            // NHEADS
#define HD        64            // HEADDIM
#define DSTATE    128
#define CONVDIM   2304          // DIN + 2*DSTATE
#define DPROJ     4384          // 2*DIN + 2*DSTATE + NH
#define MROWS     (BB*LSEQ)     // 8192

typedef unsigned long long ull;

// ---------------- scratch (static __device__, no allocs) ----------------
__device__ float g_zxbcdt[(size_t)MROWS * DPROJ];
__device__ float g_xc[(size_t)MROWS * CONVDIM];
__device__ float g_y[(size_t)MROWS * DIN];
__device__ float g_dt[(size_t)MROWS * NH];
__device__ float g_dA[(size_t)MROWS * NH];

// bf16 split operands
__device__ __nv_bfloat16 g_ahi[(size_t)MROWS * DMODEL];
__device__ __nv_bfloat16 g_alo[(size_t)MROWS * DMODEL];
__device__ __nv_bfloat16 g_w1hi[(size_t)DPROJ * DMODEL];  // W_in^T  [N][K]
__device__ __nv_bfloat16 g_w1lo[(size_t)DPROJ * DMODEL];
__device__ __nv_bfloat16 g_yhi[(size_t)MROWS * DIN];
__device__ __nv_bfloat16 g_ylo[(size_t)MROWS * DIN];
__device__ __nv_bfloat16 g_w2hi[(size_t)DMODEL * DIN];    // W_out^T [N][K]
__device__ __nv_bfloat16 g_w2lo[(size_t)DMODEL * DIN];

// ---------------- f32x2 helpers ----------------
__device__ __forceinline__ ull ffma2(ull a, ull b, ull c) {
    ull d; asm("fma.rn.f32x2 %0, %1, %2, %3;" : "=l"(d) : "l"(a), "l"(b), "l"(c)); return d;
}
__device__ __forceinline__ ull fmul2(ull a, ull b) {
    ull d; asm("mul.rn.f32x2 %0, %1, %2;" : "=l"(d) : "l"(a), "l"(b)); return d;
}
__device__ __forceinline__ ull pack2(float lo, float hi) {
    ull r; asm("mov.b64 %0, {%1, %2};" : "=l"(r) : "f"(lo), "f"(hi)); return r;
}
__device__ __forceinline__ float2 unpack2(ull v) {
    float2 f; asm("mov.b64 {%0, %1}, %2;" : "=f"(f.x), "=f"(f.y) : "l"(v)); return f;
}

// ---------------- mma.sync / ldmatrix / cp.async helpers ----------------
__device__ __forceinline__ uint32_t smem_u32(const void* p) {
    uint32_t a;
    asm("{ .reg .u64 t; cvta.to.shared.u64 t, %1; cvt.u32.u64 %0, t; }" : "=r"(a) : "l"(p));
    return a;
}
__device__ __forceinline__ void ldsm4(uint32_t& r0, uint32_t& r1, uint32_t& r2, uint32_t& r3,
                                      uint32_t addr) {
    asm volatile("ldmatrix.sync.aligned.m8n8.x4.shared.b16 {%0,%1,%2,%3}, [%4];"
                 : "=r"(r0), "=r"(r1), "=r"(r2), "=r"(r3) : "r"(addr));
}
__device__ __forceinline__ void mma16816(float* c, uint32_t a0, uint32_t a1, uint32_t a2,
                                         uint32_t a3, uint32_t b0, uint32_t b1) {
    asm volatile(
        "mma.sync.aligned.m16n8k16.row.col.f32.bf16.bf16.f32 "
        "{%0,%1,%2,%3}, {%4,%5,%6,%7}, {%8,%9}, {%0,%1,%2,%3};"
        : "+f"(c[0]), "+f"(c[1]), "+f"(c[2]), "+f"(c[3])
        : "r"(a0), "r"(a1), "r"(a2), "r"(a3), "r"(b0), "r"(b1));
}
__device__ __forceinline__ void cp16(uint32_t saddr, const void* gaddr, uint32_t srcbytes) {
    asm volatile("cp.async.cg.shared.global [%0], [%1], 16, %2;"
                 :: "r"(saddr), "l"(gaddr), "r"(srcbytes));
}
__device__ __forceinline__ void cp4(uint32_t saddr, const void* gaddr) {
    asm volatile("cp.async.ca.shared.global [%0], [%1], 4;"
                 :: "r"(saddr), "l"(gaddr));
}
__device__ __forceinline__ void cp_commit() { asm volatile("cp.async.commit_group;"); }
template <int N_> __device__ __forceinline__ void cp_wait() {
    asm volatile("cp.async.wait_group %0;" :: "n"(N_));
}

// ---------------- split / transpose-split converters ----------------
__global__ void __launch_bounds__(256)
convert_split(const float* __restrict__ src, __nv_bfloat16* __restrict__ hi,
              __nv_bfloat16* __restrict__ lo, int n4)
{
    int i = blockIdx.x * 256 + threadIdx.x;
    if (i >= n4) return;
    float4 v = ((const float4*)src)[i];
    __nv_bfloat16 h0 = __float2bfloat16(v.x), h1 = __float2bfloat16(v.y);
    __nv_bfloat16 h2 = __float2bfloat16(v.z), h3 = __float2bfloat16(v.w);
    __nv_bfloat162 H0; H0.x = h0; H0.y = h1;
    __nv_bfloat162 H1; H1.x = h2; H1.y = h3;
    ((__nv_bfloat162*)hi)[i*2]   = H0;
    ((__nv_bfloat162*)hi)[i*2+1] = H1;
    __nv_bfloat162 L0, L1;
    L0.x = __float2bfloat16(v.x - __bfloat162float(h0));
    L0.y = __float2bfloat16(v.y - __bfloat162float(h1));
    L1.x = __float2bfloat16(v.z - __bfloat162float(h2));
    L1.y = __float2bfloat16(v.w - __bfloat162float(h3));
    ((__nv_bfloat162*)lo)[i*2]   = L0;
    ((__nv_bfloat162*)lo)[i*2+1] = L1;
}

// src [K][N] fp32 -> hiT/loT [N][K] bf16 split
__global__ void __launch_bounds__(256)
transpose_split(const float* __restrict__ src, __nv_bfloat16* __restrict__ hiT,
                __nv_bfloat16* __restrict__ loT, int K, int N)
{
    __shared__ float t[32][33];
    const int kb = blockIdx.y * 32, nb = blockIdx.x * 32;
    const int tx = threadIdx.x & 31, ty = threadIdx.x >> 5;
#pragma unroll
    for (int j = 0; j < 4; j++)
        t[ty + j*8][tx] = src[(size_t)(kb + ty + j*8) * N + nb + tx];
    __syncthreads();
#pragma unroll
    for (int j = 0; j < 4; j++) {
        const int n = nb + ty + j*8, k = kb + tx;
        const float v = t[tx][ty + j*8];
        const __nv_bfloat16 h = __float2bfloat16(v);
        hiT[(size_t)n * K + k] = h;
        loT[(size_t)n * K + k] = __float2bfloat16(v - __bfloat162float(h));
    }
}

// ---------------- HMMA GEMM (frozen — measured 687us on GEMM1) ---------------
#define GS_STRIDE 80
#define GS_TILE   (128 * GS_STRIDE)
#define GS_BUF    (4 * GS_TILE)
#define GS_DYN    (2 * GS_BUF)

__global__ void __launch_bounds__(256)
gemm_hmma(const __nv_bfloat16* __restrict__ Ahi, const __nv_bfloat16* __restrict__ Alo,
          const __nv_bfloat16* __restrict__ BhiT, const __nv_bfloat16* __restrict__ BloT,
          float* __restrict__ C, int N, int K)
{
    extern __shared__ char smem[];
    const uint32_t sb = smem_u32(smem);

    const int tid = threadIdx.x;
    const int lane = tid & 31;
    const int wid = tid >> 5;
    const int warp_m = wid & 1;
    const int warp_n = wid >> 1;
    const int rowBase = blockIdx.y << 7;
    const int colBase = blockIdx.x << 7;
    const int nkc = K >> 5;

    float acc[4][4][4];
#pragma unroll
    for (int i = 0; i < 4; i++)
#pragma unroll
        for (int j = 0; j < 4; j++)
#pragma unroll
            for (int q = 0; q < 4; q++) acc[i][j][q] = 0.f;

    auto load_chunk = [&](int kc, int buf) {
        const uint32_t base = sb + (uint32_t)buf * GS_BUF;
#pragma unroll
        for (int it = 0; it < 2; it++) {
            const int id = tid + it * 256;
            const int row = id >> 2, c = id & 3;
            const size_t g = (size_t)(rowBase + row) * K + kc * 32 + c * 8;
            const uint32_t so = (uint32_t)(row * GS_STRIDE + c * 16);
            cp16(base + so,            Ahi + g, 16);
            cp16(base + GS_TILE + so,  Alo + g, 16);
        }
#pragma unroll
        for (int it = 0; it < 2; it++) {
            const int id = tid + it * 256;
            const int row = id >> 2, c = id & 3;
            const int n = colBase + row;
            const int nn = (n < N) ? n : 0;
            const uint32_t valid = (n < N) ? 16u : 0u;
            const size_t g = (size_t)nn * K + kc * 32 + c * 8;
            const uint32_t so = (uint32_t)(row * GS_STRIDE + c * 16);
            cp16(base + 2*GS_TILE + so, BhiT + g, valid);
            cp16(base + 3*GS_TILE + so, BloT + g, valid);
        }
    };

    load_chunk(0, 0);
    cp_commit();

    for (int kc = 0; kc < nkc; kc++) {
        const int buf = kc & 1;
        if (kc + 1 < nkc) {
            load_chunk(kc + 1, buf ^ 1);
            cp_commit();
            cp_wait<1>();
        } else {
            cp_wait<0>();
        }
        __syncthreads();

        const uint32_t base = sb + (uint32_t)buf * GS_BUF;
        const uint32_t aHb = base;
        const uint32_t aLb = base + GS_TILE;
        const uint32_t bHb = base + 2 * GS_TILE;
        const uint32_t bLb = base + 3 * GS_TILE;

#pragma unroll
        for (int ks = 0; ks < 2; ks++) {
            const int kb = ks * 16;
            const uint32_t loff = (uint32_t)((lane & 15) * GS_STRIDE + kb * 2 + (lane >> 4) * 16);

            uint32_t aH[4][4], aL[4][4];
#pragma unroll
            for (int mt = 0; mt < 4; mt++) {
                const uint32_t ro = (uint32_t)((warp_m * 64 + mt * 16) * GS_STRIDE) + loff;
                ldsm4(aH[mt][0], aH[mt][1], aH[mt][2], aH[mt][3], aHb + ro);
                ldsm4(aL[mt][0], aL[mt][1], aL[mt][2], aL[mt][3], aLb + ro);
            }
            uint32_t bH[4][2], bL[4][2];
#pragma unroll
            for (int np = 0; np < 2; np++) {
                const uint32_t ro = (uint32_t)((warp_n * 32 + np * 16) * GS_STRIDE) + loff;
                uint32_t r0, r1, r2, r3;
                ldsm4(r0, r1, r2, r3, bHb + ro);
                bH[np*2][0] = r0; bH[np*2][1] = r2;
                bH[np*2+1][0] = r1; bH[np*2+1][1] = r3;
                ldsm4(r0, r1, r2, r3, bLb + ro);
                bL[np*2][0] = r0; bL[np*2][1] = r2;
                bL[np*2+1][0] = r1; bL[np*2+1][1] = r3;
            }
#pragma unroll
            for (int mt = 0; mt < 4; mt++)
#pragma unroll
                for (int nt = 0; nt < 4; nt++) {
                    mma16816(acc[mt][nt], aH[mt][0], aH[mt][1], aH[mt][2], aH[mt][3],
                             bH[nt][0], bH[nt][1]);
                    mma16816(acc[mt][nt], aH[mt][0], aH[mt][1], aH[mt][2], aH[mt][3],
                             bL[nt][0], bL[nt][1]);
                    mma16816(acc[mt][nt], aL[mt][0], aL[mt][1], aL[mt][2], aL[mt][3],
                             bH[nt][0], bH[nt][1]);
                }
        }
        __syncthreads();
    }

    const int g = lane >> 2, tg = lane & 3;
#pragma unroll
    for (int mt = 0; mt < 4; mt++) {
#pragma unroll
        for (int nt = 0; nt < 4; nt++) {
            const int col = colBase + warp_n * 32 + nt * 8 + tg * 2;
            if (col < N) {
                const int r0 = rowBase + warp_m * 64 + mt * 16 + g;
                float2 v0 = make_float2(acc[mt][nt][0], acc[mt][nt][1]);
                float2 v1 = make_float2(acc[mt][nt][2], acc[mt][nt][3]);
                *(float2*)(C + (size_t)r0 * N + col)       = v0;
                *(float2*)(C + (size_t)(r0 + 8) * N + col) = v1;
            }
        }
    }
}

// ---------------- conv(4) + SiLU: 8 timesteps per CTA (sliding window) -------
__global__ void __launch_bounds__(256)
conv_kernel(const float* __restrict__ conv_w, const float* __restrict__ conv_b)
{
    const int bl0 = blockIdx.x * 8;
    const int l0  = bl0 & (LSEQ - 1);
    const int tid = threadIdx.x;
    const float* base = g_zxbcdt + (size_t)bl0 * DPROJ + DIN;
    float* out = g_xc + (size_t)bl0 * CONVDIM;

    for (int c = tid; c < CONVDIM; c += 256) {
        const float4 w = *(const float4*)(conv_w + c * 4);
        const float bias = conv_b[c];
        float v[11];
#pragma unroll
        for (int k = 0; k < 11; k++) {
            const int ll = l0 + k - 3;
            v[k] = (ll >= 0) ? base[(ptrdiff_t)(k - 3) * DPROJ + c] : 0.f;
        }
#pragma unroll
        for (int j = 0; j < 8; j++) {
            const float a = bias + w.x * v[j] + w.y * v[j+1] + w.z * v[j+2] + w.w * v[j+3];
            out[(size_t)j * CONVDIM + c] = a / (1.f + expf(-a));
        }
    }
}

// ---------------- dt / dA ----------------
__global__ void __launch_bounds__(256)
dt_kernel(const float* __restrict__ dt_bias, const float* __restrict__ A_log)
{
    const int idx = blockIdx.x * 256 + threadIdx.x;
    const int bl = idx >> 5, hh = idx & 31;
    const float v = g_zxbcdt[(size_t)bl * DPROJ + (DPROJ - NH) + hh] + dt_bias[hh];
    const float dtv = (v > 20.f) ? v : log1pf(expf(v));
    g_dt[idx] = dtv;
    g_dA[idx] = expf(-expf(A_log[hh]) * dtv);
}

// ---------------- selective scan: 512 threads, 4-stage x 4-timestep pipeline -
// thread: p = tid>>3 (0..63), nc = tid&7 (16-state chunk). 16 states = 8 ull regs.
// chunk stride 20 floats: start banks {0,20,8,28,16,4,24,12} -> conflict-free LDS.128.
#define SC_STAGES 4
#define SC_STEPS  4     // timesteps per stage
__global__ void __launch_bounds__(512)
scan_kernel(const float* __restrict__ Dv)
{
    const int h = blockIdx.x, b = blockIdx.y;
    const int tid = threadIdx.x;
    const int nc = tid & 7, p = tid >> 3;

    const float* xc  = g_xc + (size_t)b * LSEQ * CONVDIM;
    const float* dAp = g_dA + (size_t)b * LSEQ * NH + h;
    const float* dtp = g_dt + (size_t)b * LSEQ * NH + h;
    float* yout = g_y + (size_t)b * LSEQ * DIN + h * HD + p;

    __shared__ __align__(16) float sB[SC_STAGES][SC_STEPS][160];
    __shared__ __align__(16) float sC[SC_STAGES][SC_STEPS][160];
    __shared__ __align__(16) float sx[SC_STAGES][SC_STEPS][64];
    __shared__ float sdA[SC_STAGES][SC_STEPS];
    __shared__ float sdt[SC_STAGES][SC_STEPS];

    // loader: 80 cp16 per step (B:32, C:32, x:16) + 2 cp4 -> 4 steps = 328 threads
    auto load_stage = [&](int slot, int l0) {
        if (tid < 320) {
            const int j = tid / 80, op = tid % 80;
            const float* row = xc + (size_t)(l0 + j) * CONVDIM;
            if (op < 64) {
                const int isC = op >> 5, o = op & 31;
                const int chunk = o >> 2, w = o & 3;
                const float* src = row + DIN + isC * DSTATE + chunk * 16 + w * 4;
                float* dstf = (isC ? &sC[slot][j][0] : &sB[slot][j][0]) + chunk * 20 + w * 4;
                cp16(smem_u32(dstf), src, 16);
            } else {
                const int o = op - 64;
                cp16(smem_u32(&sx[slot][j][o * 4]), row + h * HD + o * 4, 16);
            }
        } else if (tid < 328) {
            const int t = tid - 320, j = t >> 1;
            if (t & 1) cp4(smem_u32(&sdt[slot][j]), dtp + (size_t)(l0 + j) * NH);
            else       cp4(smem_u32(&sdA[slot][j]), dAp + (size_t)(l0 + j) * NH);
        }
    };

    ull hs[8];
#pragma unroll
    for (int i = 0; i < 8; i++) hs[i] = 0ull;
    const float Dh = Dv[h];

#pragma unroll
    for (int s = 0; s < SC_STAGES; s++) { load_stage(s, SC_STEPS * s); cp_commit(); }

    const int niter = LSEQ / SC_STEPS;
    for (int it = 0; it < niter; it++) {
        const int slot = it & (SC_STAGES - 1);
        cp_wait<SC_STAGES - 1>();
        __syncthreads();

#pragma unroll
        for (int j = 0; j < SC_STEPS; j++) {
            const float dAv = sdA[slot][j];
            const float dtv = sdt[slot][j];
            const float xv  = sx[slot][j][p];
            const float sv  = dtv * xv;
            const ull dA2 = pack2(dAv, dAv);
            const ull s2  = pack2(sv, sv);

            const ulonglong2* B2 = (const ulonglong2*)(&sB[slot][j][nc * 20]);
            const ulonglong2* C2 = (const ulonglong2*)(&sC[slot][j][nc * 20]);
            ull acc0 = 0ull, acc1 = 0ull;
#pragma unroll
            for (int i = 0; i < 4; i++) {
                ulonglong2 bb = B2[i], cc = C2[i];
                hs[2*i]   = ffma2(dA2, hs[2*i],   fmul2(s2, bb.x));
                acc0      = ffma2(hs[2*i],   cc.x, acc0);
                hs[2*i+1] = ffma2(dA2, hs[2*i+1], fmul2(s2, bb.y));
                acc1      = ffma2(hs[2*i+1], cc.y, acc1);
            }
            float2 f0 = unpack2(acc0), f1 = unpack2(acc1);
            float r = (f0.x + f0.y) + (f1.x + f1.y);
            r += __shfl_xor_sync(0xffffffffu, r, 1);
            r += __shfl_xor_sync(0xffffffffu, r, 2);
            r += __shfl_xor_sync(0xffffffffu, r, 4);
            if (nc == 0) yout[(size_t)(SC_STEPS * it + j) * DIN] = r + Dh * xv;
        }
        __syncthreads();
        if (it + SC_STAGES < niter) load_stage(slot, SC_STEPS * (it + SC_STAGES));
        cp_commit();
    }
}

// ---------------- gating + RMSNorm -> bf16 hi/lo split ----------------
__global__ void __launch_bounds__(256)
gate_norm_kernel(const float* __restrict__ norm_w)
{
    const int bl = blockIdx.x;
    const float* yrow = g_y + (size_t)bl * DIN;
    const float* zrow = g_zxbcdt + (size_t)bl * DPROJ;
    __nv_bfloat16* hrow = g_yhi + (size_t)bl * DIN;
    __nv_bfloat16* lrow = g_ylo + (size_t)bl * DIN;
    const int tid = threadIdx.x;

    float v[8];
    float ss = 0.f;
#pragma unroll
    for (int j = 0; j < 8; j++) {
        const int c = tid + j * 256;
        const float z = zrow[c];
        const float val = yrow[c] * (z / (1.f + expf(-z)));
        v[j] = val;
        ss += val * val;
    }
#pragma unroll
    for (int o = 16; o; o >>= 1) ss += __shfl_xor_sync(0xffffffffu, ss, o);
    __shared__ float red[8];
    if ((tid & 31) == 0) red[tid >> 5] = ss;
    __syncthreads();
    float tot = 0.f;
#pragma unroll
    for (int i = 0; i < 8; i++) tot += red[i];
    const float scale = rsqrtf(tot * (1.f / (float)DIN) + 1e-5f);
#pragma unroll
    for (int j = 0; j < 8; j++) {
        const int c = tid + j * 256;
        const float o = v[j] * scale * norm_w[c];
        const __nv_bfloat16 hh = __float2bfloat16(o);
        hrow[c] = hh;
        lrow[c] = __float2bfloat16(o - __bfloat162float(hh));
    }
}

// ---------------- launch ----------------
extern "C" void kernel_launch(void* const* d_in, const int* in_sizes, int n_in,
                              void* d_out, int out_size)
{
    (void)in_sizes; (void)n_in; (void)out_size;

    const float* hidden  = (const float*)d_in[0];
    const float* W_in    = (const float*)d_in[1];
    const float* conv_w  = (const float*)d_in[2];
    const float* conv_b  = (const float*)d_in[3];
    const float* dt_bias = (const float*)d_in[4];
    const float* A_log   = (const float*)d_in[5];
    const float* Dvec    = (const float*)d_in[6];
    const float* norm_w  = (const float*)d_in[7];
    const float* W_out   = (const float*)d_in[8];
    float* out = (float*)d_out;

    static float* zx = nullptr;
    static __nv_bfloat16 *ahi, *alo, *w1hi, *w1lo, *yhi, *ylo, *w2hi, *w2lo;
    if (!zx) {
        void* p;
        cudaGetSymbolAddress(&p, g_zxbcdt); zx  = (float*)p;
        cudaGetSymbolAddress(&p, g_ahi);  ahi  = (__nv_bfloat16*)p;
        cudaGetSymbolAddress(&p, g_alo);  alo  = (__nv_bfloat16*)p;
        cudaGetSymbolAddress(&p, g_w1hi); w1hi = (__nv_bfloat16*)p;
        cudaGetSymbolAddress(&p, g_w1lo); w1lo = (__nv_bfloat16*)p;
        cudaGetSymbolAddress(&p, g_yhi);  yhi  = (__nv_bfloat16*)p;
        cudaGetSymbolAddress(&p, g_ylo);  ylo  = (__nv_bfloat16*)p;
        cudaGetSymbolAddress(&p, g_w2hi); w2hi = (__nv_bfloat16*)p;
        cudaGetSymbolAddress(&p, g_w2lo); w2lo = (__nv_bfloat16*)p;
        cudaFuncSetAttribute(gemm_hmma, cudaFuncAttributeMaxDynamicSharedMemorySize, GS_DYN);
    }

    // 0) operand prep
    {
        const int n4 = MROWS * DMODEL / 4;
        convert_split<<<(n4 + 255) / 256, 256>>>(hidden, ahi, alo, n4);
    }
    transpose_split<<<dim3(DPROJ / 32, DMODEL / 32), 256>>>(W_in, w1hi, w1lo, DMODEL, DPROJ);
    transpose_split<<<dim3(DMODEL / 32, DIN / 32), 256>>>(W_out, w2hi, w2lo, DIN, DMODEL);

    // 1) zxbcdt = hidden @ W_in
    gemm_hmma<<<dim3((DPROJ + 127) / 128, MROWS / 128), 256, GS_DYN>>>(
        ahi, alo, w1hi, w1lo, zx, DPROJ, DMODEL);

    // 2) conv + silu (8 steps/CTA) and dt/dA
    conv_kernel<<<MROWS / 8, 256>>>(conv_w, conv_b);
    dt_kernel<<<MROWS * NH / 256, 256>>>(dt_bias, A_log);

    // 3) selective scan (512 threads, 4x4 pipeline)
    scan_kernel<<<dim3(NH, BB), 512>>>(Dvec);

    // 4) gating + rmsnorm -> bf16 hi/lo
    gate_norm_kernel<<<MROWS, 256>>>(norm_w);

    // 5) out = y @ W_out
    gemm_hmma<<<dim3(DMODEL / 128, MROWS / 128), 256, GS_DYN>>>(
        yhi, ylo, w2hi, w2lo, out, DMODEL, DIN);
}

// round 9
// speedup vs baseline: 2.9287x; 1.0937x over previous
#include <cuda_runtime.h>
#include <cuda_bf16.h>
#include <math.h>
#include <stdint.h>

// ---------------- problem constants ----------------
#define BB        4
#define LSEQ      2048
#define DMODEL    1024
#define DIN       2048          // D_INNER
#define NH        32            // NHEADS
#define HD        64            // HEADDIM
#define DSTATE    128
#define CONVDIM   2304          // DIN + 2*DSTATE
#define DPROJ     4384          // 2*DIN + 2*DSTATE + NH
#define MROWS     (BB*LSEQ)     // 8192

typedef unsigned long long ull;

// ---------------- scratch (static __device__, no allocs) ----------------
__device__ float g_zxbcdt[(size_t)MROWS * DPROJ];
__device__ float g_xc[(size_t)MROWS * CONVDIM];
__device__ float g_y[(size_t)MROWS * DIN];
__device__ float g_dt[(size_t)MROWS * NH];
__device__ float g_dA[(size_t)MROWS * NH];

// bf16 split operands
__device__ __nv_bfloat16 g_ahi[(size_t)MROWS * DMODEL];
__device__ __nv_bfloat16 g_alo[(size_t)MROWS * DMODEL];
__device__ __nv_bfloat16 g_w1hi[(size_t)DPROJ * DMODEL];  // W_in^T  [N][K]
__device__ __nv_bfloat16 g_w1lo[(size_t)DPROJ * DMODEL];
__device__ __nv_bfloat16 g_yhi[(size_t)MROWS * DIN];
__device__ __nv_bfloat16 g_ylo[(size_t)MROWS * DIN];
__device__ __nv_bfloat16 g_w2hi[(size_t)DMODEL * DIN];    // W_out^T [N][K]
__device__ __nv_bfloat16 g_w2lo[(size_t)DMODEL * DIN];

// ---------------- f32x2 helpers ----------------
__device__ __forceinline__ ull ffma2(ull a, ull b, ull c) {
    ull d; asm("fma.rn.f32x2 %0, %1, %2, %3;" : "=l"(d) : "l"(a), "l"(b), "l"(c)); return d;
}
__device__ __forceinline__ ull fmul2(ull a, ull b) {
    ull d; asm("mul.rn.f32x2 %0, %1, %2;" : "=l"(d) : "l"(a), "l"(b)); return d;
}
__device__ __forceinline__ ull pack2(float lo, float hi) {
    ull r; asm("mov.b64 %0, {%1, %2};" : "=l"(r) : "f"(lo), "f"(hi)); return r;
}
__device__ __forceinline__ float2 unpack2(ull v) {
    float2 f; asm("mov.b64 {%0, %1}, %2;" : "=f"(f.x), "=f"(f.y) : "l"(v)); return f;
}

// ---------------- mma.sync / ldmatrix / cp.async helpers ----------------
__device__ __forceinline__ uint32_t smem_u32(const void* p) {
    uint32_t a;
    asm("{ .reg .u64 t; cvta.to.shared.u64 t, %1; cvt.u32.u64 %0, t; }" : "=r"(a) : "l"(p));
    return a;
}
__device__ __forceinline__ void ldsm4(uint32_t& r0, uint32_t& r1, uint32_t& r2, uint32_t& r3,
                                      uint32_t addr) {
    asm volatile("ldmatrix.sync.aligned.m8n8.x4.shared.b16 {%0,%1,%2,%3}, [%4];"
                 : "=r"(r0), "=r"(r1), "=r"(r2), "=r"(r3) : "r"(addr));
}
__device__ __forceinline__ void mma16816(float* c, uint32_t a0, uint32_t a1, uint32_t a2,
                                         uint32_t a3, uint32_t b0, uint32_t b1) {
    asm volatile(
        "mma.sync.aligned.m16n8k16.row.col.f32.bf16.bf16.f32 "
        "{%0,%1,%2,%3}, {%4,%5,%6,%7}, {%8,%9}, {%0,%1,%2,%3};"
        : "+f"(c[0]), "+f"(c[1]), "+f"(c[2]), "+f"(c[3])
        : "r"(a0), "r"(a1), "r"(a2), "r"(a3), "r"(b0), "r"(b1));
}
__device__ __forceinline__ void cp16(uint32_t saddr, const void* gaddr, uint32_t srcbytes) {
    asm volatile("cp.async.cg.shared.global [%0], [%1], 16, %2;"
                 :: "r"(saddr), "l"(gaddr), "r"(srcbytes));
}
__device__ __forceinline__ void cp4(uint32_t saddr, const void* gaddr) {
    asm volatile("cp.async.ca.shared.global [%0], [%1], 4;"
                 :: "r"(saddr), "l"(gaddr));
}
__device__ __forceinline__ void cp_commit() { asm volatile("cp.async.commit_group;"); }
template <int N_> __device__ __forceinline__ void cp_wait() {
    asm volatile("cp.async.wait_group %0;" :: "n"(N_));
}

// ---------------- split / transpose-split converters ----------------
__global__ void __launch_bounds__(256)
convert_split(const float* __restrict__ src, __nv_bfloat16* __restrict__ hi,
              __nv_bfloat16* __restrict__ lo, int n4)
{
    int i = blockIdx.x * 256 + threadIdx.x;
    if (i >= n4) return;
    float4 v = ((const float4*)src)[i];
    __nv_bfloat16 h0 = __float2bfloat16(v.x), h1 = __float2bfloat16(v.y);
    __nv_bfloat16 h2 = __float2bfloat16(v.z), h3 = __float2bfloat16(v.w);
    __nv_bfloat162 H0; H0.x = h0; H0.y = h1;
    __nv_bfloat162 H1; H1.x = h2; H1.y = h3;
    ((__nv_bfloat162*)hi)[i*2]   = H0;
    ((__nv_bfloat162*)hi)[i*2+1] = H1;
    __nv_bfloat162 L0, L1;
    L0.x = __float2bfloat16(v.x - __bfloat162float(h0));
    L0.y = __float2bfloat16(v.y - __bfloat162float(h1));
    L1.x = __float2bfloat16(v.z - __bfloat162float(h2));
    L1.y = __float2bfloat16(v.w - __bfloat162float(h3));
    ((__nv_bfloat162*)lo)[i*2]   = L0;
    ((__nv_bfloat162*)lo)[i*2+1] = L1;
}

// src [K][N] fp32 -> hiT/loT [N][K] bf16 split
__global__ void __launch_bounds__(256)
transpose_split(const float* __restrict__ src, __nv_bfloat16* __restrict__ hiT,
                __nv_bfloat16* __restrict__ loT, int K, int N)
{
    __shared__ float t[32][33];
    const int kb = blockIdx.y * 32, nb = blockIdx.x * 32;
    const int tx = threadIdx.x & 31, ty = threadIdx.x >> 5;
#pragma unroll
    for (int j = 0; j < 4; j++)
        t[ty + j*8][tx] = src[(size_t)(kb + ty + j*8) * N + nb + tx];
    __syncthreads();
#pragma unroll
    for (int j = 0; j < 4; j++) {
        const int n = nb + ty + j*8, k = kb + tx;
        const float v = t[tx][ty + j*8];
        const __nv_bfloat16 h = __float2bfloat16(v);
        hiT[(size_t)n * K + k] = h;
        loT[(size_t)n * K + k] = __float2bfloat16(v - __bfloat162float(h));
    }
}

// ---------------- HMMA GEMM (frozen — measured 683us on GEMM1) ---------------
#define GS_STRIDE 80
#define GS_TILE   (128 * GS_STRIDE)
#define GS_BUF    (4 * GS_TILE)
#define GS_DYN    (2 * GS_BUF)

__global__ void __launch_bounds__(256)
gemm_hmma(const __nv_bfloat16* __restrict__ Ahi, const __nv_bfloat16* __restrict__ Alo,
          const __nv_bfloat16* __restrict__ BhiT, const __nv_bfloat16* __restrict__ BloT,
          float* __restrict__ C, int N, int K)
{
    extern __shared__ char smem[];
    const uint32_t sb = smem_u32(smem);

    const int tid = threadIdx.x;
    const int lane = tid & 31;
    const int wid = tid >> 5;
    const int warp_m = wid & 1;
    const int warp_n = wid >> 1;
    const int rowBase = blockIdx.y << 7;
    const int colBase = blockIdx.x << 7;
    const int nkc = K >> 5;

    float acc[4][4][4];
#pragma unroll
    for (int i = 0; i < 4; i++)
#pragma unroll
        for (int j = 0; j < 4; j++)
#pragma unroll
            for (int q = 0; q < 4; q++) acc[i][j][q] = 0.f;

    auto load_chunk = [&](int kc, int buf) {
        const uint32_t base = sb + (uint32_t)buf * GS_BUF;
#pragma unroll
        for (int it = 0; it < 2; it++) {
            const int id = tid + it * 256;
            const int row = id >> 2, c = id & 3;
            const size_t g = (size_t)(rowBase + row) * K + kc * 32 + c * 8;
            const uint32_t so = (uint32_t)(row * GS_STRIDE + c * 16);
            cp16(base + so,            Ahi + g, 16);
            cp16(base + GS_TILE + so,  Alo + g, 16);
        }
#pragma unroll
        for (int it = 0; it < 2; it++) {
            const int id = tid + it * 256;
            const int row = id >> 2, c = id & 3;
            const int n = colBase + row;
            const int nn = (n < N) ? n : 0;
            const uint32_t valid = (n < N) ? 16u : 0u;
            const size_t g = (size_t)nn * K + kc * 32 + c * 8;
            const uint32_t so = (uint32_t)(row * GS_STRIDE + c * 16);
            cp16(base + 2*GS_TILE + so, BhiT + g, valid);
            cp16(base + 3*GS_TILE + so, BloT + g, valid);
        }
    };

    load_chunk(0, 0);
    cp_commit();

    for (int kc = 0; kc < nkc; kc++) {
        const int buf = kc & 1;
        if (kc + 1 < nkc) {
            load_chunk(kc + 1, buf ^ 1);
            cp_commit();
            cp_wait<1>();
        } else {
            cp_wait<0>();
        }
        __syncthreads();

        const uint32_t base = sb + (uint32_t)buf * GS_BUF;
        const uint32_t aHb = base;
        const uint32_t aLb = base + GS_TILE;
        const uint32_t bHb = base + 2 * GS_TILE;
        const uint32_t bLb = base + 3 * GS_TILE;

#pragma unroll
        for (int ks = 0; ks < 2; ks++) {
            const int kb = ks * 16;
            const uint32_t loff = (uint32_t)((lane & 15) * GS_STRIDE + kb * 2 + (lane >> 4) * 16);

            uint32_t aH[4][4], aL[4][4];
#pragma unroll
            for (int mt = 0; mt < 4; mt++) {
                const uint32_t ro = (uint32_t)((warp_m * 64 + mt * 16) * GS_STRIDE) + loff;
                ldsm4(aH[mt][0], aH[mt][1], aH[mt][2], aH[mt][3], aHb + ro);
                ldsm4(aL[mt][0], aL[mt][1], aL[mt][2], aL[mt][3], aLb + ro);
            }
            uint32_t bH[4][2], bL[4][2];
#pragma unroll
            for (int np = 0; np < 2; np++) {
                const uint32_t ro = (uint32_t)((warp_n * 32 + np * 16) * GS_STRIDE) + loff;
                uint32_t r0, r1, r2, r3;
                ldsm4(r0, r1, r2, r3, bHb + ro);
                bH[np*2][0] = r0; bH[np*2][1] = r2;
                bH[np*2+1][0] = r1; bH[np*2+1][1] = r3;
                ldsm4(r0, r1, r2, r3, bLb + ro);
                bL[np*2][0] = r0; bL[np*2][1] = r2;
                bL[np*2+1][0] = r1; bL[np*2+1][1] = r3;
            }
#pragma unroll
            for (int mt = 0; mt < 4; mt++)
#pragma unroll
                for (int nt = 0; nt < 4; nt++) {
                    mma16816(acc[mt][nt], aH[mt][0], aH[mt][1], aH[mt][2], aH[mt][3],
                             bH[nt][0], bH[nt][1]);
                    mma16816(acc[mt][nt], aH[mt][0], aH[mt][1], aH[mt][2], aH[mt][3],
                             bL[nt][0], bL[nt][1]);
                    mma16816(acc[mt][nt], aL[mt][0], aL[mt][1], aL[mt][2], aL[mt][3],
                             bH[nt][0], bH[nt][1]);
                }
        }
        __syncthreads();
    }

    const int g = lane >> 2, tg = lane & 3;
#pragma unroll
    for (int mt = 0; mt < 4; mt++) {
#pragma unroll
        for (int nt = 0; nt < 4; nt++) {
            const int col = colBase + warp_n * 32 + nt * 8 + tg * 2;
            if (col < N) {
                const int r0 = rowBase + warp_m * 64 + mt * 16 + g;
                float2 v0 = make_float2(acc[mt][nt][0], acc[mt][nt][1]);
                float2 v1 = make_float2(acc[mt][nt][2], acc[mt][nt][3]);
                *(float2*)(C + (size_t)r0 * N + col)       = v0;
                *(float2*)(C + (size_t)(r0 + 8) * N + col) = v1;
            }
        }
    }
}

// ---------------- conv(4) + SiLU: 8 timesteps per CTA (sliding window) -------
__global__ void __launch_bounds__(256)
conv_kernel(const float* __restrict__ conv_w, const float* __restrict__ conv_b)
{
    const int bl0 = blockIdx.x * 8;
    const int l0  = bl0 & (LSEQ - 1);
    const int tid = threadIdx.x;
    const float* base = g_zxbcdt + (size_t)bl0 * DPROJ + DIN;
    float* out = g_xc + (size_t)bl0 * CONVDIM;

    for (int c = tid; c < CONVDIM; c += 256) {
        const float4 w = *(const float4*)(conv_w + c * 4);
        const float bias = conv_b[c];
        float v[11];
#pragma unroll
        for (int k = 0; k < 11; k++) {
            const int ll = l0 + k - 3;
            v[k] = (ll >= 0) ? base[(ptrdiff_t)(k - 3) * DPROJ + c] : 0.f;
        }
#pragma unroll
        for (int j = 0; j < 8; j++) {
            const float a = bias + w.x * v[j] + w.y * v[j+1] + w.z * v[j+2] + w.w * v[j+3];
            out[(size_t)j * CONVDIM + c] = a / (1.f + expf(-a));
        }
    }
}

// ---------------- dt / dA ----------------
__global__ void __launch_bounds__(256)
dt_kernel(const float* __restrict__ dt_bias, const float* __restrict__ A_log)
{
    const int idx = blockIdx.x * 256 + threadIdx.x;
    const int bl = idx >> 5, hh = idx & 31;
    const float v = g_zxbcdt[(size_t)bl * DPROJ + (DPROJ - NH) + hh] + dt_bias[hh];
    const float dtv = (v > 20.f) ? v : log1pf(expf(v));
    g_dt[idx] = dtv;
    g_dA[idx] = expf(-expf(A_log[hh]) * dtv);
}

// ---------------- selective scan: 256 threads, 2p x 16n per thread ----------
// Key change vs R8: each thread owns TWO p-rows sharing one B/C chunk read ->
// smem delivered bytes per step halve (67KB -> 35KB); chunk stride 20 floats
// puts the 8 chunks' 16B lines on all 32 banks exactly once (conflict-free).
#define SC_STAGES 4
#define SC_STEPS  4
__global__ void __launch_bounds__(256)
scan_kernel(const float* __restrict__ Dv)
{
    const int h = blockIdx.x, b = blockIdx.y;
    const int tid = threadIdx.x;
    const int nc = tid & 7;          // n-chunk (16 states)
    const int pg = tid >> 3;         // p-group (2 rows): p0 = 2*pg
    const int p0 = pg * 2;

    const float* xc  = g_xc + (size_t)b * LSEQ * CONVDIM;
    const float* dAp = g_dA + (size_t)b * LSEQ * NH + h;
    const float* dtp = g_dt + (size_t)b * LSEQ * NH + h;
    float* yout = g_y + (size_t)b * LSEQ * DIN + h * HD + p0;

    // chunk stride 20 floats (80B, 16B-aligned); 8 chunks x 20 = 160 floats
    __shared__ __align__(16) float sB[SC_STAGES][SC_STEPS][160];
    __shared__ __align__(16) float sC[SC_STAGES][SC_STEPS][160];
    __shared__ __align__(16) float sx[SC_STAGES][SC_STEPS][64];
    __shared__ float sdA[SC_STAGES][SC_STEPS];
    __shared__ float sdt[SC_STAGES][SC_STEPS];

    // loader: per step 80 cp16 (B 32, C 32, x 16) + 2 cp4; 4 steps = 328 ops,
    // covered by 256 threads x 2 passes.
    auto load_stage = [&](int slot, int l0) {
#pragma unroll
        for (int pass = 0; pass < 2; pass++) {
            const int idx = tid + pass * 256;
            if (idx < 320) {
                const int j = idx / 80, op = idx % 80;
                const float* row = xc + (size_t)(l0 + j) * CONVDIM;
                if (op < 64) {
                    const int isC = op >> 5, o = op & 31;
                    const int chunk = o >> 2, q = o & 3;
                    const float* src = row + DIN + isC * DSTATE + chunk * 16 + q * 4;
                    float* dstf = (isC ? &sC[slot][j][0] : &sB[slot][j][0]) + chunk * 20 + q * 4;
                    cp16(smem_u32(dstf), src, 16);
                } else {
                    const int o = op - 64;
                    cp16(smem_u32(&sx[slot][j][o * 4]), row + h * HD + o * 4, 16);
                }
            } else if (idx < 328) {
                const int t = idx - 320, j = t >> 1;
                if (t & 1) cp4(smem_u32(&sdt[slot][j]), dtp + (size_t)(l0 + j) * NH);
                else       cp4(smem_u32(&sdA[slot][j]), dAp + (size_t)(l0 + j) * NH);
            }
        }
    };

    ull hs0[8], hs1[8];
#pragma unroll
    for (int i = 0; i < 8; i++) { hs0[i] = 0ull; hs1[i] = 0ull; }
    const float Dh = Dv[h];

#pragma unroll
    for (int s = 0; s < SC_STAGES; s++) { load_stage(s, SC_STEPS * s); cp_commit(); }

    const int niter = LSEQ / SC_STEPS;
    for (int it = 0; it < niter; it++) {
        const int slot = it & (SC_STAGES - 1);
        cp_wait<SC_STAGES - 1>();
        __syncthreads();

#pragma unroll
        for (int j = 0; j < SC_STEPS; j++) {
            const float dAv = sdA[slot][j];
            const float dtv = sdt[slot][j];
            const float2 xv = *(const float2*)&sx[slot][j][p0];
            const float s0 = dtv * xv.x, s1 = dtv * xv.y;
            const ull dA2 = pack2(dAv, dAv);
            const ull s20 = pack2(s0, s0);
            const ull s21 = pack2(s1, s1);

            const ulonglong2* B2 = (const ulonglong2*)(&sB[slot][j][nc * 20]);
            const ulonglong2* C2 = (const ulonglong2*)(&sC[slot][j][nc * 20]);
            ull acc0 = 0ull, acc1 = 0ull;
#pragma unroll
            for (int i = 0; i < 4; i++) {
                const ulonglong2 bb = B2[i], cc = C2[i];
                hs0[2*i]   = ffma2(dA2, hs0[2*i],   fmul2(s20, bb.x));
                acc0       = ffma2(hs0[2*i],   cc.x, acc0);
                hs1[2*i]   = ffma2(dA2, hs1[2*i],   fmul2(s21, bb.x));
                acc1       = ffma2(hs1[2*i],   cc.x, acc1);
                hs0[2*i+1] = ffma2(dA2, hs0[2*i+1], fmul2(s20, bb.y));
                acc0       = ffma2(hs0[2*i+1], cc.y, acc0);
                hs1[2*i+1] = ffma2(dA2, hs1[2*i+1], fmul2(s21, bb.y));
                acc1       = ffma2(hs1[2*i+1], cc.y, acc1);
            }
            const float2 f0 = unpack2(acc0), f1 = unpack2(acc1);
            float r0 = f0.x + f0.y;
            float r1 = f1.x + f1.y;
#pragma unroll
            for (int o = 1; o < 8; o <<= 1) {
                r0 += __shfl_xor_sync(0xffffffffu, r0, o);
                r1 += __shfl_xor_sync(0xffffffffu, r1, o);
            }
            if (nc == 0) {
                float2 ov;
                ov.x = r0 + Dh * xv.x;
                ov.y = r1 + Dh * xv.y;
                *(float2*)(yout + (size_t)(SC_STEPS * it + j) * DIN) = ov;
            }
        }
        __syncthreads();
        if (it + SC_STAGES < niter) load_stage(slot, SC_STEPS * (it + SC_STAGES));
        cp_commit();
    }
}

// ---------------- gating + RMSNorm -> bf16 hi/lo split ----------------
__global__ void __launch_bounds__(256)
gate_norm_kernel(const float* __restrict__ norm_w)
{
    const int bl = blockIdx.x;
    const float* yrow = g_y + (size_t)bl * DIN;
    const float* zrow = g_zxbcdt + (size_t)bl * DPROJ;
    __nv_bfloat16* hrow = g_yhi + (size_t)bl * DIN;
    __nv_bfloat16* lrow = g_ylo + (size_t)bl * DIN;
    const int tid = threadIdx.x;

    float v[8];
    float ss = 0.f;
#pragma unroll
    for (int j = 0; j < 8; j++) {
        const int c = tid + j * 256;
        const float z = zrow[c];
        const float val = yrow[c] * (z / (1.f + expf(-z)));
        v[j] = val;
        ss += val * val;
    }
#pragma unroll
    for (int o = 16; o; o >>= 1) ss += __shfl_xor_sync(0xffffffffu, ss, o);
    __shared__ float red[8];
    if ((tid & 31) == 0) red[tid >> 5] = ss;
    __syncthreads();
    float tot = 0.f;
#pragma unroll
    for (int i = 0; i < 8; i++) tot += red[i];
    const float scale = rsqrtf(tot * (1.f / (float)DIN) + 1e-5f);
#pragma unroll
    for (int j = 0; j < 8; j++) {
        const int c = tid + j * 256;
        const float o = v[j] * scale * norm_w[c];
        const __nv_bfloat16 hh = __float2bfloat16(o);
        hrow[c] = hh;
        lrow[c] = __float2bfloat16(o - __bfloat162float(hh));
    }
}

// ---------------- launch ----------------
extern "C" void kernel_launch(void* const* d_in, const int* in_sizes, int n_in,
                              void* d_out, int out_size)
{
    (void)in_sizes; (void)n_in; (void)out_size;

    const float* hidden  = (const float*)d_in[0];
    const float* W_in    = (const float*)d_in[1];
    const float* conv_w  = (const float*)d_in[2];
    const float* conv_b  = (const float*)d_in[3];
    const float* dt_bias = (const float*)d_in[4];
    const float* A_log   = (const float*)d_in[5];
    const float* Dvec    = (const float*)d_in[6];
    const float* norm_w  = (const float*)d_in[7];
    const float* W_out   = (const float*)d_in[8];
    float* out = (float*)d_out;

    static float* zx = nullptr;
    static __nv_bfloat16 *ahi, *alo, *w1hi, *w1lo, *yhi, *ylo, *w2hi, *w2lo;
    if (!zx) {
        void* p;
        cudaGetSymbolAddress(&p, g_zxbcdt); zx  = (float*)p;
        cudaGetSymbolAddress(&p, g_ahi);  ahi  = (__nv_bfloat16*)p;
        cudaGetSymbolAddress(&p, g_alo);  alo  = (__nv_bfloat16*)p;
        cudaGetSymbolAddress(&p, g_w1hi); w1hi = (__nv_bfloat16*)p;
        cudaGetSymbolAddress(&p, g_w1lo); w1lo = (__nv_bfloat16*)p;
        cudaGetSymbolAddress(&p, g_yhi);  yhi  = (__nv_bfloat16*)p;
        cudaGetSymbolAddress(&p, g_ylo);  ylo  = (__nv_bfloat16*)p;
        cudaGetSymbolAddress(&p, g_w2hi); w2hi = (__nv_bfloat16*)p;
        cudaGetSymbolAddress(&p, g_w2lo); w2lo = (__nv_bfloat16*)p;
        cudaFuncSetAttribute(gemm_hmma, cudaFuncAttributeMaxDynamicSharedMemorySize, GS_DYN);
    }

    // 0) operand prep
    {
        const int n4 = MROWS * DMODEL / 4;
        convert_split<<<(n4 + 255) / 256, 256>>>(hidden, ahi, alo, n4);
    }
    transpose_split<<<dim3(DPROJ / 32, DMODEL / 32), 256>>>(W_in, w1hi, w1lo, DMODEL, DPROJ);
    transpose_split<<<dim3(DMODEL / 32, DIN / 32), 256>>>(W_out, w2hi, w2lo, DIN, DMODEL);

    // 1) zxbcdt = hidden @ W_in
    gemm_hmma<<<dim3((DPROJ + 127) / 128, MROWS / 128), 256, GS_DYN>>>(
        ahi, alo, w1hi, w1lo, zx, DPROJ, DMODEL);

    // 2) conv + silu (8 steps/CTA) and dt/dA
    conv_kernel<<<MROWS / 8, 256>>>(conv_w, conv_b);
    dt_kernel<<<MROWS * NH / 256, 256>>>(dt_bias, A_log);

    // 3) selective scan (2p x 16n per thread, halved smem traffic)
    scan_kernel<<<dim3(NH, BB), 256>>>(Dvec);

    // 4) gating + rmsnorm -> bf16 hi/lo
    gate_norm_kernel<<<MROWS, 256>>>(norm_w);

    // 5) out = y @ W_out
    gemm_hmma<<<dim3(DMODEL / 128, MROWS / 128), 256, GS_DYN>>>(
        yhi, ylo, w2hi, w2lo, out, DMODEL, DIN);
}